// round 1
// baseline (speedup 1.0000x reference)
#include <cuda_runtime.h>
#include <math.h>

#define Bv 64
#define Tv 512
#define Hv 512
#define FH 2048   /* 4*H */

#define NCTA 128
#define NTHR 256

// ---------------- device scratch (allocation-free rule: __device__ globals) ----
__device__ float g_xproj[Bv * Tv * FH];   // 256 MB: x-projection for current layer
__device__ float g_out0[Bv * Tv * Hv];    // 64 MB: layer-0 sequence output
__device__ float g_hbuf[2][Bv * Hv];      // double-buffered hidden state
__device__ unsigned long long g_bar_cnt = 0ULL;
__device__ unsigned long long g_bar_gen = 0ULL;

// ---------------- software grid barrier (monotonic generations, 64-bit) -------
__device__ __forceinline__ void grid_barrier() {
    __syncthreads();
    if (threadIdx.x == 0) {
        __threadfence();
        unsigned long long old = atomicAdd(&g_bar_cnt, 1ULL);
        unsigned long long gen = old / (unsigned long long)NCTA;
        if (old % (unsigned long long)NCTA == (unsigned long long)(NCTA - 1)) {
            *(volatile unsigned long long*)&g_bar_gen = gen + 1ULL;
        } else {
            while (*(volatile unsigned long long*)&g_bar_gen <= gen) { }
            __threadfence();
        }
    }
    __syncthreads();
}

// ---------------- SGEMM: C[M,2048] = A[M,512] * B[512,2048], fp32 ------------
// 128x128 tile, BK=8, 256 threads, 8x8 register tile.
__global__ __launch_bounds__(256, 2)
void sgemm_k(const float* __restrict__ A_ext,
             const float* __restrict__ Bw,
             int use_g_out0)
{
    const float* A = use_g_out0 ? g_out0 : A_ext;
    float* C = g_xproj;

    __shared__ float As[8][132];
    __shared__ float Bs[8][128];

    const int tid = threadIdx.x;
    const int bn = blockIdx.x;     // 0..15
    const int bm = blockIdx.y;     // 0..255
    const int tx = tid & 15;
    const int ty = tid >> 4;
    const int m0 = ty * 8;
    const int n0 = tx * 8;

    const int arow = tid >> 1;            // 0..127
    const int akq  = (tid & 1) * 4;       // 0 or 4
    const int brow = tid >> 5;            // 0..7
    const int bc   = (tid & 31) * 4;      // 0..124

    float acc[8][8];
#pragma unroll
    for (int i = 0; i < 8; ++i)
#pragma unroll
        for (int j = 0; j < 8; ++j) acc[i][j] = 0.f;

    for (int k0 = 0; k0 < 512; k0 += 8) {
        float4 av = *(const float4*)&A[(size_t)(bm * 128 + arow) * 512 + k0 + akq];
        float4 bv = *(const float4*)&Bw[(size_t)(k0 + brow) * FH + bn * 128 + bc];
        As[akq + 0][arow] = av.x;
        As[akq + 1][arow] = av.y;
        As[akq + 2][arow] = av.z;
        As[akq + 3][arow] = av.w;
        *(float4*)&Bs[brow][bc] = bv;
        __syncthreads();

#pragma unroll
        for (int kk = 0; kk < 8; ++kk) {
            float a[8], b[8];
            *(float4*)&a[0] = *(const float4*)&As[kk][m0];
            *(float4*)&a[4] = *(const float4*)&As[kk][m0 + 4];
            *(float4*)&b[0] = *(const float4*)&Bs[kk][n0];
            *(float4*)&b[4] = *(const float4*)&Bs[kk][n0 + 4];
#pragma unroll
            for (int i = 0; i < 8; ++i)
#pragma unroll
                for (int j = 0; j < 8; ++j)
                    acc[i][j] = fmaf(a[i], b[j], acc[i][j]);
        }
        __syncthreads();
    }

#pragma unroll
    for (int i = 0; i < 8; ++i) {
        float* cp = &C[(size_t)(bm * 128 + m0 + i) * FH + bn * 128 + n0];
        float4 v0 = make_float4(acc[i][0], acc[i][1], acc[i][2], acc[i][3]);
        float4 v1 = make_float4(acc[i][4], acc[i][5], acc[i][6], acc[i][7]);
        *(float4*)cp = v0;
        *(float4*)(cp + 4) = v1;
    }
}

// ---------------- persistent recurrent LSTM layer ----------------------------
// 128 CTAs x 256 threads, each CTA owns 4 hidden columns (16 z-columns over the
// 4 gates). Wh slice cached in smem for all T steps; h staged in smem per step;
// c kept CTA-local in smem. One grid barrier per timestep.
__global__ __launch_bounds__(NTHR, 1)
void lstm_layer_kernel(const float* __restrict__ Wh,
                       const float* __restrict__ bvec,
                       const float* __restrict__ h_in,
                       const float* __restrict__ c_in,
                       float* __restrict__ seq_out_ext, int seq_to_internal,
                       float* __restrict__ hT_out,
                       float* __restrict__ cT_out)
{
    extern __shared__ float smem[];
    float* w_s = smem;                   // [16][516]
    float* h_s = smem + 16 * 516;        // [64][516]
    float* z_s = h_s + 64 * 516;         // [64][16]
    float* c_s = z_s + 64 * 16;          // [256]

    float* seq_out = seq_to_internal ? g_out0 : seq_out_ext;
    const float* xp = g_xproj;

    const int tid = threadIdx.x;
    const int n0 = blockIdx.x * 4;       // base hidden column for this CTA

    // Load Wh slice: w_s[c][k], c = gate*4 + j  -> global col gate*H + n0 + j
    for (int idx = tid; idx < 16 * 512; idx += NTHR) {
        int cc = idx >> 9;
        int k = idx & 511;
        int col = (cc >> 2) * Hv + n0 + (cc & 3);
        w_s[cc * 516 + k] = Wh[(size_t)k * FH + col];
    }
    // c state, local to CTA
    for (int idx = tid; idx < 256; idx += NTHR) {
        int b = idx >> 2, j = idx & 3;
        c_s[idx] = c_in[b * Hv + n0 + j];
    }
    // seed h double-buffer (each CTA writes its own columns)
    for (int idx = tid; idx < 256; idx += NTHR) {
        int b = idx >> 2, j = idx & 3;
        __stcg(&g_hbuf[0][b * Hv + n0 + j], h_in[b * Hv + n0 + j]);
    }
    const float bgi = bvec[0] + bvec[1];
    const float bgf = bvec[2] + bvec[3];
    const float bgg = bvec[4] + bvec[5];
    const float bgo = bvec[6] + bvec[7];

    grid_barrier();

    const int cpair = tid & 7;       // column pair 0..7
    const int bq = tid >> 3;         // batch pair 0..31
    const int c0 = cpair * 2;
    const int b0 = bq * 2;

    for (int t = 0; t < Tv; ++t) {
        const float* hsrc = g_hbuf[t & 1];
        float* hdst = g_hbuf[(t & 1) ^ 1];

        // Stage full h into smem (L2-coherent loads)
        for (int idx = tid * 4; idx < Bv * Hv; idx += NTHR * 4) {
            float4 v = __ldcg((const float4*)(hsrc + idx));
            int b = idx >> 9;
            int k = idx & 511;
            *(float4*)(h_s + b * 516 + k) = v;
        }
        __syncthreads();

        // z tile: 2 batches x 2 columns per thread over K=512
        float a00 = 0.f, a01 = 0.f, a10 = 0.f, a11 = 0.f;
        const float4* h0p = (const float4*)(h_s + b0 * 516);
        const float4* h1p = (const float4*)(h_s + (b0 + 1) * 516);
        const float4* w0p = (const float4*)(w_s + c0 * 516);
        const float4* w1p = (const float4*)(w_s + (c0 + 1) * 516);
#pragma unroll 4
        for (int kq = 0; kq < 128; ++kq) {
            float4 h0 = h0p[kq], h1 = h1p[kq];
            float4 w0 = w0p[kq], w1 = w1p[kq];
            a00 = fmaf(h0.x, w0.x, a00); a00 = fmaf(h0.y, w0.y, a00);
            a00 = fmaf(h0.z, w0.z, a00); a00 = fmaf(h0.w, w0.w, a00);
            a01 = fmaf(h0.x, w1.x, a01); a01 = fmaf(h0.y, w1.y, a01);
            a01 = fmaf(h0.z, w1.z, a01); a01 = fmaf(h0.w, w1.w, a01);
            a10 = fmaf(h1.x, w0.x, a10); a10 = fmaf(h1.y, w0.y, a10);
            a10 = fmaf(h1.z, w0.z, a10); a10 = fmaf(h1.w, w0.w, a10);
            a11 = fmaf(h1.x, w1.x, a11); a11 = fmaf(h1.y, w1.y, a11);
            a11 = fmaf(h1.z, w1.z, a11); a11 = fmaf(h1.w, w1.w, a11);
        }
        z_s[b0 * 16 + c0]           = a00;
        z_s[b0 * 16 + c0 + 1]       = a01;
        z_s[(b0 + 1) * 16 + c0]     = a10;
        z_s[(b0 + 1) * 16 + c0 + 1] = a11;
        __syncthreads();

        // Gate epilogue: thread -> (b, j), j in 0..3 hidden column offset
        {
            int b = tid >> 2, j = tid & 3;
            int xbase = (b * Tv + t) * FH + n0 + j;
            float zi = z_s[b * 16 + 0 + j]  + xp[xbase]          + bgi;
            float zf = z_s[b * 16 + 4 + j]  + xp[xbase + Hv]     + bgf;
            float zg = z_s[b * 16 + 8 + j]  + xp[xbase + 2 * Hv] + bgg;
            float zo = z_s[b * 16 + 12 + j] + xp[xbase + 3 * Hv] + bgo;
            float ig = 1.f / (1.f + __expf(-zi));
            float fg = 1.f / (1.f + __expf(-zf));
            float gg = tanhf(zg);
            float og = 1.f / (1.f + __expf(-zo));
            float cn = fmaf(fg, c_s[tid], ig * gg);
            c_s[tid] = cn;
            float hn = og * tanhf(cn);
            __stcg(&hdst[b * Hv + n0 + j], hn);
            seq_out[(size_t)(b * Tv + t) * Hv + n0 + j] = hn;
            if (t == Tv - 1) {
                hT_out[b * Hv + n0 + j] = hn;
                cT_out[b * Hv + n0 + j] = cn;
            }
        }
        grid_barrier();
    }
}

// ---------------- launch -----------------------------------------------------
extern "C" void kernel_launch(void* const* d_in, const int* in_sizes, int n_in,
                              void* d_out, int out_size)
{
    const float* x   = (const float*)d_in[0];
    const float* h   = (const float*)d_in[1];
    const float* c   = (const float*)d_in[2];
    const float* Wx0 = (const float*)d_in[3];
    const float* Wh0 = (const float*)d_in[4];
    const float* b0  = (const float*)d_in[5];
    const float* Wx1 = (const float*)d_in[6];
    const float* Wh1 = (const float*)d_in[7];
    const float* b1  = (const float*)d_in[8];
    float* out = (float*)d_out;

    const int SMEM_BYTES = (16 * 516 + 64 * 516 + 64 * 16 + 256) * 4;  // 170240
    cudaFuncSetAttribute(lstm_layer_kernel,
                         cudaFuncAttributeMaxDynamicSharedMemorySize, SMEM_BYTES);

    float* out1 = out;                                   // [B,T,H]
    float* newh = out + (size_t)Bv * Tv * Hv;            // [2,B,H]
    float* newc = newh + 2 * Bv * Hv;                    // [2,B,H]

    dim3 gg(FH / 128, (Bv * Tv) / 128);   // (16, 256)

    // Layer 0
    sgemm_k<<<gg, 256>>>(x, Wx0, 0);
    lstm_layer_kernel<<<NCTA, NTHR, SMEM_BYTES>>>(
        Wh0, b0, h, c, nullptr, 1, newh, newc);

    // Layer 1
    sgemm_k<<<gg, 256>>>(nullptr, Wx1, 1);
    lstm_layer_kernel<<<NCTA, NTHR, SMEM_BYTES>>>(
        Wh1, b1, h + Bv * Hv, c + Bv * Hv, out1, 0,
        newh + Bv * Hv, newc + Bv * Hv);
}

// round 2
// speedup vs baseline: 1.2724x; 1.2724x over previous
#include <cuda_runtime.h>
#include <math.h>

#define Bv 64
#define Tv 512
#define Hv 512
#define FH 2048   /* 4*H */

#define NCTA 128
#define NTHR 256

typedef unsigned long long ull;

// ---------------- device scratch ---------------------------------------------
__device__ float g_xproj[Bv * Tv * FH];   // x-projection for current layer
__device__ float g_out0[Bv * Tv * Hv];    // layer-0 sequence output
__device__ float g_hT[2][Hv * Bv];        // transposed hidden state [k][b], dbl-buffered
__device__ unsigned long long g_bar_cnt = 0ULL;
__device__ unsigned long long g_bar_gen = 0ULL;

// ---------------- packed f32x2 helpers ---------------------------------------
__device__ __forceinline__ ull ffma2(ull a, ull b, ull c) {
    ull d;
    asm("fma.rn.f32x2 %0, %1, %2, %3;" : "=l"(d) : "l"(a), "l"(b), "l"(c));
    return d;
}
__device__ __forceinline__ ull fadd2(ull a, ull b) {
    ull d;
    asm("add.rn.f32x2 %0, %1, %2;" : "=l"(d) : "l"(a), "l"(b));
    return d;
}
__device__ __forceinline__ ull fdup(float x) {
    ull d;
    asm("mov.b64 %0, {%1, %1};" : "=l"(d) : "f"(x));
    return d;
}

// ---------------- software grid barrier --------------------------------------
__device__ __forceinline__ void grid_barrier() {
    __syncthreads();
    if (threadIdx.x == 0) {
        __threadfence();
        unsigned long long old = atomicAdd(&g_bar_cnt, 1ULL);
        unsigned long long gen = old / (unsigned long long)NCTA;
        if (old % (unsigned long long)NCTA == (unsigned long long)(NCTA - 1)) {
            *(volatile unsigned long long*)&g_bar_gen = gen + 1ULL;
        } else {
            while (*(volatile unsigned long long*)&g_bar_gen <= gen) { }
            __threadfence();
        }
    }
    __syncthreads();
}

// ---------------- SGEMM: C[M,2048] = A[M,512] * B[512,2048], fp32 (f32x2) ----
__global__ __launch_bounds__(256, 2)
void sgemm_k(const float* __restrict__ A_ext,
             const float* __restrict__ Bw,
             int use_g_out0)
{
    const float* A = use_g_out0 ? g_out0 : A_ext;
    float* C = g_xproj;

    __shared__ float As[8][132];
    __shared__ float Bs[8][128];

    const int tid = threadIdx.x;
    const int bn = blockIdx.x;     // 0..15
    const int bm = blockIdx.y;     // 0..255
    const int tx = tid & 15;
    const int ty = tid >> 4;
    const int m0 = ty * 8;
    const int n0 = tx * 8;

    const int arow = tid >> 1;
    const int akq  = (tid & 1) * 4;
    const int brow = tid >> 5;
    const int bc   = (tid & 31) * 4;

    ull acc[8][4];
#pragma unroll
    for (int i = 0; i < 8; ++i)
#pragma unroll
        for (int j = 0; j < 4; ++j) acc[i][j] = 0ULL;

    for (int k0 = 0; k0 < 512; k0 += 8) {
        float4 av = *(const float4*)&A[(size_t)(bm * 128 + arow) * 512 + k0 + akq];
        float4 bv = *(const float4*)&Bw[(size_t)(k0 + brow) * FH + bn * 128 + bc];
        As[akq + 0][arow] = av.x;
        As[akq + 1][arow] = av.y;
        As[akq + 2][arow] = av.z;
        As[akq + 3][arow] = av.w;
        *(float4*)&Bs[brow][bc] = bv;
        __syncthreads();

#pragma unroll
        for (int kk = 0; kk < 8; ++kk) {
            float a[8];
            *(float4*)&a[0] = *(const float4*)&As[kk][m0];
            *(float4*)&a[4] = *(const float4*)&As[kk][m0 + 4];
            ulonglong2 b01 = *(const ulonglong2*)&Bs[kk][n0];
            ulonglong2 b23 = *(const ulonglong2*)&Bs[kk][n0 + 4];
#pragma unroll
            for (int i = 0; i < 8; ++i) {
                ull ad = fdup(a[i]);
                acc[i][0] = ffma2(ad, b01.x, acc[i][0]);
                acc[i][1] = ffma2(ad, b01.y, acc[i][1]);
                acc[i][2] = ffma2(ad, b23.x, acc[i][2]);
                acc[i][3] = ffma2(ad, b23.y, acc[i][3]);
            }
        }
        __syncthreads();
    }

#pragma unroll
    for (int i = 0; i < 8; ++i) {
        float* cp = &C[(size_t)(bm * 128 + m0 + i) * FH + bn * 128 + n0];
        *(ulonglong2*)cp = make_ulonglong2(acc[i][0], acc[i][1]);
        *(ulonglong2*)(cp + 4) = make_ulonglong2(acc[i][2], acc[i][3]);
    }
}

// ---------------- persistent recurrent LSTM layer ----------------------------
// 128 CTAs x 256 threads. CTA owns 4 hidden cols (16 z-cols). K-split 16 with
// 8x8 per-thread tiles (1 B/FMA smem traffic), packed f32x2 FMAs, butterfly
// shuffle reduction across k-slices. h kept transposed ([k][b]) globally and
// in smem (pad-68 rows, conflict-free LDS.128).
__global__ __launch_bounds__(NTHR, 1)
void lstm_layer_kernel(const float* __restrict__ Wh,
                       const float* __restrict__ bvec,
                       const float* __restrict__ h_in,
                       const float* __restrict__ c_in,
                       float* __restrict__ seq_out_ext, int seq_to_internal,
                       float* __restrict__ hT_out,
                       float* __restrict__ cT_out)
{
    extern __shared__ float smem[];
    float* w_s = smem;                     // [512][20] (16 used)
    float* h_s = smem + 512 * 20;          // [512][68] (64 used)
    float* z_s = h_s + 512 * 68;           // [64][16]
    float* c_s = z_s + 64 * 16;            // [256]

    float* seq_out = seq_to_internal ? g_out0 : seq_out_ext;
    const float* xp = g_xproj;

    const int tid = threadIdx.x;
    const int n0 = blockIdx.x * 4;         // base hidden column of this CTA

    // Wh slice: w_s[k*20 + c], c = gate*4 + j  ->  Wh[k][gate*H + n0 + j]
    for (int idx = tid; idx < 512 * 16; idx += NTHR) {
        int k = idx >> 4, cc = idx & 15;
        w_s[k * 20 + cc] = Wh[(size_t)k * FH + (cc >> 2) * Hv + n0 + (cc & 3)];
    }
    // c state + transposed h seed
    for (int idx = tid; idx < 256; idx += NTHR) {
        int b = idx >> 2, j = idx & 3;
        c_s[idx] = c_in[b * Hv + n0 + j];
        __stcg(&g_hT[0][(n0 + j) * Bv + b], h_in[b * Hv + n0 + j]);
    }
    const float bgi = bvec[0] + bvec[1];
    const float bgf = bvec[2] + bvec[3];
    const float bgg = bvec[4] + bvec[5];
    const float bgo = bvec[6] + bvec[7];

    grid_barrier();

    const int tile = tid >> 4;             // 0..15
    const int ksl  = tid & 15;             // 0..15 (k-slice; contiguous lanes)
    const int b0 = (tile >> 1) * 8;        // batch-tile base
    const int c0 = (tile & 1) * 8;         // col-tile base
    const int eb = tid >> 2, ej = tid & 3; // epilogue mapping

    for (int t = 0; t < Tv; ++t) {
        const float* hsrc = g_hT[t & 1];
        float* hdst = g_hT[(t & 1) ^ 1];

        // Stage h [512][64] -> h_s [512][68] (L2-coherent loads)
        for (int q = tid; q < (Hv * Bv) / 4; q += NTHR) {
            float4 v = __ldcg((const float4*)hsrc + q);
            int k = q >> 4, bq = q & 15;
            *(float4*)&h_s[k * 68 + bq * 4] = v;
        }
        // Prefetch x-projection for the epilogue
        int xbase = (eb * Tv + t) * FH + n0 + ej;
        float x0 = xp[xbase];
        float x1 = xp[xbase + Hv];
        float x2 = xp[xbase + 2 * Hv];
        float x3 = xp[xbase + 3 * Hv];
        __syncthreads();

        // 8x8 tile, k = ksl + 16*i, i = 0..31
        ull acc[8][4];
#pragma unroll
        for (int bi = 0; bi < 8; ++bi)
#pragma unroll
            for (int p = 0; p < 4; ++p) acc[bi][p] = 0ULL;

#pragma unroll 4
        for (int i = 0; i < 32; ++i) {
            int k = ksl + (i << 4);
            float hv[8];
            *(float4*)&hv[0] = *(const float4*)&h_s[k * 68 + b0];
            *(float4*)&hv[4] = *(const float4*)&h_s[k * 68 + b0 + 4];
            ulonglong2 w01 = *(const ulonglong2*)&w_s[k * 20 + c0];
            ulonglong2 w23 = *(const ulonglong2*)&w_s[k * 20 + c0 + 4];
#pragma unroll
            for (int bi = 0; bi < 8; ++bi) {
                ull hd = fdup(hv[bi]);
                acc[bi][0] = ffma2(hd, w01.x, acc[bi][0]);
                acc[bi][1] = ffma2(hd, w01.y, acc[bi][1]);
                acc[bi][2] = ffma2(hd, w23.x, acc[bi][2]);
                acc[bi][3] = ffma2(hd, w23.y, acc[bi][3]);
            }
        }

        // Butterfly reduction over the 16 k-slice lanes
#pragma unroll
        for (int m = 8; m >= 1; m >>= 1) {
#pragma unroll
            for (int bi = 0; bi < 8; ++bi)
#pragma unroll
                for (int p = 0; p < 4; ++p) {
                    ull o = __shfl_xor_sync(0xffffffffu, acc[bi][p], m);
                    acc[bi][p] = fadd2(acc[bi][p], o);
                }
        }
        // Lanes ksl 0..7 write one batch-row of the tile each
        if (ksl < 8) {
            float* zpq = &z_s[(b0 + ksl) * 16 + c0];
            *(ulonglong2*)zpq = make_ulonglong2(acc[ksl][0], acc[ksl][1]);
            *(ulonglong2*)(zpq + 4) = make_ulonglong2(acc[ksl][2], acc[ksl][3]);
        }
        __syncthreads();

        // Gate epilogue: thread -> (b, j)
        {
            float zi = z_s[eb * 16 + 0  + ej] + x0 + bgi;
            float zf = z_s[eb * 16 + 4  + ej] + x1 + bgf;
            float zg = z_s[eb * 16 + 8  + ej] + x2 + bgg;
            float zo = z_s[eb * 16 + 12 + ej] + x3 + bgo;
            float ig = 1.f / (1.f + __expf(-zi));
            float fg = 1.f / (1.f + __expf(-zf));
            float gg = tanhf(zg);
            float og = 1.f / (1.f + __expf(-zo));
            float cn = fmaf(fg, c_s[tid], ig * gg);
            c_s[tid] = cn;
            float hn = og * tanhf(cn);
            __stcg(&hdst[(n0 + ej) * Bv + eb], hn);
            seq_out[(size_t)(eb * Tv + t) * Hv + n0 + ej] = hn;
            if (t == Tv - 1) {
                hT_out[eb * Hv + n0 + ej] = hn;
                cT_out[eb * Hv + n0 + ej] = cn;
            }
        }
        grid_barrier();
    }
}

// ---------------- launch -----------------------------------------------------
extern "C" void kernel_launch(void* const* d_in, const int* in_sizes, int n_in,
                              void* d_out, int out_size)
{
    const float* x   = (const float*)d_in[0];
    const float* h   = (const float*)d_in[1];
    const float* c   = (const float*)d_in[2];
    const float* Wx0 = (const float*)d_in[3];
    const float* Wh0 = (const float*)d_in[4];
    const float* b0  = (const float*)d_in[5];
    const float* Wx1 = (const float*)d_in[6];
    const float* Wh1 = (const float*)d_in[7];
    const float* b1  = (const float*)d_in[8];
    float* out = (float*)d_out;

    const int SMEM_BYTES = (512 * 20 + 512 * 68 + 64 * 16 + 256) * 4;  // 185344
    cudaFuncSetAttribute(lstm_layer_kernel,
                         cudaFuncAttributeMaxDynamicSharedMemorySize, SMEM_BYTES);

    float* out1 = out;                                   // [B,T,H]
    float* newh = out + (size_t)Bv * Tv * Hv;            // [2,B,H]
    float* newc = newh + 2 * Bv * Hv;                    // [2,B,H]

    dim3 gg(FH / 128, (Bv * Tv) / 128);   // (16, 256)

    // Layer 0
    sgemm_k<<<gg, 256>>>(x, Wx0, 0);
    lstm_layer_kernel<<<NCTA, NTHR, SMEM_BYTES>>>(
        Wh0, b0, h, c, nullptr, 1, newh, newc);

    // Layer 1
    sgemm_k<<<gg, 256>>>(nullptr, Wx1, 1);
    lstm_layer_kernel<<<NCTA, NTHR, SMEM_BYTES>>>(
        Wh1, b1, h + Bv * Hv, c + Bv * Hv, out1, 0,
        newh + Bv * Hv, newc + Bv * Hv);
}

// round 3
// speedup vs baseline: 1.6968x; 1.3335x over previous
#include <cuda_runtime.h>
#include <math.h>

#define Bv 64
#define Tv 512
#define Hv 512
#define FH 2048   /* 4*H */

#define NCTA 128
#define NTHR 512

typedef unsigned long long ull;

// ---------------- device scratch ---------------------------------------------
__device__ float g_xproj[Bv * Tv * FH];   // x-projection for current layer
__device__ float g_out0[Bv * Tv * Hv];    // layer-0 sequence output
__device__ float g_hT[2][Hv * Bv];        // transposed hidden state [k][b], dbl-buffered
__device__ unsigned long long g_bar_cnt = 0ULL;
__device__ unsigned long long g_bar_gen = 0ULL;

// ---------------- packed f32x2 helpers ---------------------------------------
__device__ __forceinline__ ull ffma2(ull a, ull b, ull c) {
    ull d;
    asm("fma.rn.f32x2 %0, %1, %2, %3;" : "=l"(d) : "l"(a), "l"(b), "l"(c));
    return d;
}
__device__ __forceinline__ ull fadd2(ull a, ull b) {
    ull d;
    asm("add.rn.f32x2 %0, %1, %2;" : "=l"(d) : "l"(a), "l"(b));
    return d;
}
__device__ __forceinline__ ull fdup(float x) {
    ull d;
    asm("mov.b64 %0, {%1, %1};" : "=l"(d) : "f"(x));
    return d;
}

// ---------------- software grid barrier --------------------------------------
__device__ __forceinline__ void grid_barrier() {
    __syncthreads();
    if (threadIdx.x == 0) {
        __threadfence();
        unsigned long long old = atomicAdd(&g_bar_cnt, 1ULL);
        unsigned long long gen = old / (unsigned long long)NCTA;
        if (old % (unsigned long long)NCTA == (unsigned long long)(NCTA - 1)) {
            *(volatile unsigned long long*)&g_bar_gen = gen + 1ULL;
        } else {
            while (*(volatile unsigned long long*)&g_bar_gen <= gen) { }
            __threadfence();
        }
    }
    __syncthreads();
}

// ---------------- SGEMM: C[M,2048] = A[M,512] * B[512,2048] ------------------
// 128x128 tile, BK=8, 256 threads, double-buffered smem, f32x2 FMAs.
__global__ __launch_bounds__(256, 2)
void sgemm_k(const float* __restrict__ A_ext,
             const float* __restrict__ Bw,
             int use_g_out0)
{
    const float* A = use_g_out0 ? g_out0 : A_ext;
    float* C = g_xproj;

    __shared__ float As[2][8][132];
    __shared__ float Bs[2][8][128];

    const int tid = threadIdx.x;
    const int bn = blockIdx.x;     // 0..15
    const int bm = blockIdx.y;     // 0..255
    const int tx = tid & 15;
    const int ty = tid >> 4;
    const int m0 = ty * 8;
    const int n0 = tx * 8;

    const int arow = tid >> 1;
    const int akq  = (tid & 1) * 4;
    const int brow = tid >> 5;
    const int bc   = (tid & 31) * 4;

    const float* aptr = &A[(size_t)(bm * 128 + arow) * 512 + akq];
    const float* bptr = &Bw[(size_t)brow * FH + bn * 128 + bc];

    ull acc[8][4];
#pragma unroll
    for (int i = 0; i < 8; ++i)
#pragma unroll
        for (int j = 0; j < 4; ++j) acc[i][j] = 0ULL;

    // stage 0
    {
        float4 av = *(const float4*)aptr;
        float4 bv = *(const float4*)bptr;
        As[0][akq + 0][arow] = av.x;
        As[0][akq + 1][arow] = av.y;
        As[0][akq + 2][arow] = av.z;
        As[0][akq + 3][arow] = av.w;
        *(float4*)&Bs[0][brow][bc] = bv;
    }
    __syncthreads();

    int buf = 0;
    for (int k0 = 0; k0 < 512; k0 += 8) {
        float4 av_n, bv_n;
        const bool more = (k0 + 8) < 512;
        if (more) {
            av_n = *(const float4*)(aptr + k0 + 8);
            bv_n = *(const float4*)(bptr + (size_t)(k0 + 8) * FH);
        }

#pragma unroll
        for (int kk = 0; kk < 8; ++kk) {
            float a[8];
            *(float4*)&a[0] = *(const float4*)&As[buf][kk][m0];
            *(float4*)&a[4] = *(const float4*)&As[buf][kk][m0 + 4];
            ulonglong2 b01 = *(const ulonglong2*)&Bs[buf][kk][n0];
            ulonglong2 b23 = *(const ulonglong2*)&Bs[buf][kk][n0 + 4];
#pragma unroll
            for (int i = 0; i < 8; ++i) {
                ull ad = fdup(a[i]);
                acc[i][0] = ffma2(ad, b01.x, acc[i][0]);
                acc[i][1] = ffma2(ad, b01.y, acc[i][1]);
                acc[i][2] = ffma2(ad, b23.x, acc[i][2]);
                acc[i][3] = ffma2(ad, b23.y, acc[i][3]);
            }
        }

        if (more) {
            int nb = buf ^ 1;
            As[nb][akq + 0][arow] = av_n.x;
            As[nb][akq + 1][arow] = av_n.y;
            As[nb][akq + 2][arow] = av_n.z;
            As[nb][akq + 3][arow] = av_n.w;
            *(float4*)&Bs[nb][brow][bc] = bv_n;
            __syncthreads();
            buf = nb;
        }
    }

#pragma unroll
    for (int i = 0; i < 8; ++i) {
        float* cp = &C[(size_t)(bm * 128 + m0 + i) * FH + bn * 128 + n0];
        *(ulonglong2*)cp = make_ulonglong2(acc[i][0], acc[i][1]);
        *(ulonglong2*)(cp + 4) = make_ulonglong2(acc[i][2], acc[i][3]);
    }
}

// ---------------- persistent recurrent LSTM layer ----------------------------
// 128 CTAs x 512 threads (4 warps/SMSP for latency hiding). CTA owns 4 hidden
// cols (16 z-cols). 32 tiles (8 batch-tiles x 4 col-tiles) x 16 k-slices.
// Accumulators packed along BATCH: h pairs load as 64-bit directly, only w is
// duplicated (4 dups/iter). Butterfly reduce over 16 k-slice lanes.
__global__ __launch_bounds__(NTHR, 1)
void lstm_layer_kernel(const float* __restrict__ Wh,
                       const float* __restrict__ bvec,
                       const float* __restrict__ h_in,
                       const float* __restrict__ c_in,
                       float* __restrict__ seq_out_ext, int seq_to_internal,
                       float* __restrict__ hT_out,
                       float* __restrict__ cT_out)
{
    extern __shared__ float smem[];
    float* w_s = smem;                     // [512][20] (16 used)
    float* h_s = smem + 512 * 20;          // [512][68] (64 used)
    float* z_s = h_s + 512 * 68;           // [16][68]  z[c][b]
    float* c_s = z_s + 16 * 68;            // [256]

    float* seq_out = seq_to_internal ? g_out0 : seq_out_ext;
    const float* xp = g_xproj;

    const int tid = threadIdx.x;
    const int n0 = blockIdx.x * 4;         // base hidden column of this CTA

    // Wh slice: w_s[k*20 + c], c = gate*4 + j  ->  Wh[k][gate*H + n0 + j]
    for (int idx = tid; idx < 512 * 16; idx += NTHR) {
        int k = idx >> 4, cc = idx & 15;
        w_s[k * 20 + cc] = Wh[(size_t)k * FH + (cc >> 2) * Hv + n0 + (cc & 3)];
    }
    // c state + transposed h seed
    if (tid < 256) {
        int b = tid >> 2, j = tid & 3;
        c_s[tid] = c_in[b * Hv + n0 + j];
        __stcg(&g_hT[0][(n0 + j) * Bv + b], h_in[b * Hv + n0 + j]);
    }
    const float bgi = bvec[0] + bvec[1];
    const float bgf = bvec[2] + bvec[3];
    const float bgg = bvec[4] + bvec[5];
    const float bgo = bvec[6] + bvec[7];

    grid_barrier();

    const int tile = tid >> 4;             // 0..31
    const int ksl  = tid & 15;             // 0..15
    const int b0 = (tile >> 2) * 8;        // batch-tile base (8 batches)
    const int c0 = (tile & 3) * 4;         // col-tile base   (4 cols)
    const int eb = tid >> 2, ej = tid & 3; // epilogue mapping (tid<256)

    for (int t = 0; t < Tv; ++t) {
        const float* hsrc = g_hT[t & 1];
        float* hdst = g_hT[(t & 1) ^ 1];

        // Stage h [512][64] -> h_s [512][68]
        for (int q = tid; q < (Hv * Bv) / 4; q += NTHR) {
            float4 v = __ldcg((const float4*)hsrc + q);
            int k = q >> 4, bq = q & 15;
            *(float4*)&h_s[k * 68 + bq * 4] = v;
        }
        // Prefetch x-projection for the epilogue
        float x0, x1, x2, x3;
        if (tid < 256) {
            int xbase = (eb * Tv + t) * FH + n0 + ej;
            x0 = xp[xbase];
            x1 = xp[xbase + Hv];
            x2 = xp[xbase + 2 * Hv];
            x3 = xp[xbase + 3 * Hv];
        }
        __syncthreads();

        // acc[bp][cj]: batch-pair bp (2 batches packed) x col cj
        ull acc[4][4];
#pragma unroll
        for (int bp = 0; bp < 4; ++bp)
#pragma unroll
            for (int cj = 0; cj < 4; ++cj) acc[bp][cj] = 0ULL;

#pragma unroll 4
        for (int i = 0; i < 32; ++i) {
            int k = ksl + (i << 4);
            ulonglong2 h01 = *(const ulonglong2*)&h_s[k * 68 + b0];
            ulonglong2 h23 = *(const ulonglong2*)&h_s[k * 68 + b0 + 4];
            float wv[4];
            *(float4*)&wv[0] = *(const float4*)&w_s[k * 20 + c0];
#pragma unroll
            for (int cj = 0; cj < 4; ++cj) {
                ull wd = fdup(wv[cj]);
                acc[0][cj] = ffma2(h01.x, wd, acc[0][cj]);
                acc[1][cj] = ffma2(h01.y, wd, acc[1][cj]);
                acc[2][cj] = ffma2(h23.x, wd, acc[2][cj]);
                acc[3][cj] = ffma2(h23.y, wd, acc[3][cj]);
            }
        }

        // Butterfly reduction over the 16 k-slice lanes
#pragma unroll
        for (int m = 8; m >= 1; m >>= 1) {
#pragma unroll
            for (int bp = 0; bp < 4; ++bp)
#pragma unroll
                for (int cj = 0; cj < 4; ++cj) {
                    ull o = __shfl_xor_sync(0xffffffffu, acc[bp][cj], m);
                    acc[bp][cj] = fadd2(acc[bp][cj], o);
                }
        }
        // Lanes 0..7 each store 4 batches of one column: z_s[c][b]
        if (ksl < 8) {
            int cj = ksl & 3;
            int bp0 = (ksl >> 2) * 2;       // 0 or 2
            *(ulonglong2*)&z_s[(c0 + cj) * 68 + b0 + bp0 * 2] =
                make_ulonglong2(acc[bp0][cj], acc[bp0 + 1][cj]);
        }
        __syncthreads();

        // Gate epilogue: thread -> (b=eb, j=ej)
        if (tid < 256) {
            float zi = z_s[(0  + ej) * 68 + eb] + x0 + bgi;
            float zf = z_s[(4  + ej) * 68 + eb] + x1 + bgf;
            float zg = z_s[(8  + ej) * 68 + eb] + x2 + bgg;
            float zo = z_s[(12 + ej) * 68 + eb] + x3 + bgo;
            float ig = 1.f / (1.f + __expf(-zi));
            float fg = 1.f / (1.f + __expf(-zf));
            float gg = tanhf(zg);
            float og = 1.f / (1.f + __expf(-zo));
            float cn = fmaf(fg, c_s[tid], ig * gg);
            c_s[tid] = cn;
            float hn = og * tanhf(cn);
            __stcg(&hdst[(n0 + ej) * Bv + eb], hn);
            seq_out[(size_t)(eb * Tv + t) * Hv + n0 + ej] = hn;
            if (t == Tv - 1) {
                hT_out[eb * Hv + n0 + ej] = hn;
                cT_out[eb * Hv + n0 + ej] = cn;
            }
        }
        grid_barrier();
    }
}

// ---------------- launch -----------------------------------------------------
extern "C" void kernel_launch(void* const* d_in, const int* in_sizes, int n_in,
                              void* d_out, int out_size)
{
    const float* x   = (const float*)d_in[0];
    const float* h   = (const float*)d_in[1];
    const float* c   = (const float*)d_in[2];
    const float* Wx0 = (const float*)d_in[3];
    const float* Wh0 = (const float*)d_in[4];
    const float* b0  = (const float*)d_in[5];
    const float* Wx1 = (const float*)d_in[6];
    const float* Wh1 = (const float*)d_in[7];
    const float* b1  = (const float*)d_in[8];
    float* out = (float*)d_out;

    const int SMEM_BYTES = (512 * 20 + 512 * 68 + 16 * 68 + 256) * 4;  // 185600
    cudaFuncSetAttribute(lstm_layer_kernel,
                         cudaFuncAttributeMaxDynamicSharedMemorySize, SMEM_BYTES);

    float* out1 = out;                                   // [B,T,H]
    float* newh = out + (size_t)Bv * Tv * Hv;            // [2,B,H]
    float* newc = newh + 2 * Bv * Hv;                    // [2,B,H]

    dim3 gg(FH / 128, (Bv * Tv) / 128);   // (16, 256)

    // Layer 0
    sgemm_k<<<gg, 256>>>(x, Wx0, 0);
    lstm_layer_kernel<<<NCTA, NTHR, SMEM_BYTES>>>(
        Wh0, b0, h, c, nullptr, 1, newh, newc);

    // Layer 1
    sgemm_k<<<gg, 256>>>(nullptr, Wx1, 1);
    lstm_layer_kernel<<<NCTA, NTHR, SMEM_BYTES>>>(
        Wh1, b1, h + Bv * Hv, c + Bv * Hv, out1, 0,
        newh + Bv * Hv, newc + Bv * Hv);
}

// round 5
// speedup vs baseline: 1.8736x; 1.1042x over previous
#include <cuda_runtime.h>
#include <cuda_bf16.h>
#include <math.h>
#include <cstdint>

#define Bv 64
#define Tv 512
#define Hv 512
#define FH 2048   /* 4*H */

#define NCTA 128
#define NTHR 512

typedef unsigned long long ull;

// ---------------- device scratch ---------------------------------------------
__device__ float g_xproj[Bv * Tv * FH];            // x-projection for current layer
__device__ __nv_bfloat16 g_xhi[Bv * Tv * Hv];      // GEMM A operand, hi part
__device__ __nv_bfloat16 g_xlo[Bv * Tv * Hv];      // GEMM A operand, lo part
__device__ __nv_bfloat16 g_w0hi[FH * Hv];          // W_x0^T [n][k] hi
__device__ __nv_bfloat16 g_w0lo[FH * Hv];
__device__ __nv_bfloat16 g_w1hi[FH * Hv];          // W_x1^T [n][k] hi
__device__ __nv_bfloat16 g_w1lo[FH * Hv];
__device__ float g_hT[2][Hv * Bv];                 // transposed hidden state [k][b]
__device__ unsigned long long g_bar_cnt = 0ULL;
__device__ unsigned long long g_bar_gen = 0ULL;

// ---------------- helpers -----------------------------------------------------
__device__ __forceinline__ uint32_t smem_u32(const void* p) {
    uint32_t a;
    asm("{ .reg .u64 t; cvta.to.shared.u64 t, %1; cvt.u32.u64 %0, t; }" : "=r"(a) : "l"(p));
    return a;
}
__device__ __forceinline__ void ldsm_x4(uint32_t& r0, uint32_t& r1, uint32_t& r2,
                                        uint32_t& r3, uint32_t addr) {
    asm volatile("ldmatrix.sync.aligned.m8n8.x4.shared.b16 {%0,%1,%2,%3}, [%4];"
                 : "=r"(r0), "=r"(r1), "=r"(r2), "=r"(r3) : "r"(addr));
}
__device__ __forceinline__ void mma16816(float* d, const uint32_t* a, const uint32_t* b) {
    asm volatile(
        "mma.sync.aligned.m16n8k16.row.col.f32.bf16.bf16.f32 "
        "{%0,%1,%2,%3}, {%4,%5,%6,%7}, {%8,%9}, {%0,%1,%2,%3};"
        : "+f"(d[0]), "+f"(d[1]), "+f"(d[2]), "+f"(d[3])
        : "r"(a[0]), "r"(a[1]), "r"(a[2]), "r"(a[3]), "r"(b[0]), "r"(b[1]));
}

// ---------------- packed f32x2 helpers ---------------------------------------
__device__ __forceinline__ ull ffma2(ull a, ull b, ull c) {
    ull d; asm("fma.rn.f32x2 %0, %1, %2, %3;" : "=l"(d) : "l"(a), "l"(b), "l"(c)); return d;
}
__device__ __forceinline__ ull fadd2(ull a, ull b) {
    ull d; asm("add.rn.f32x2 %0, %1, %2;" : "=l"(d) : "l"(a), "l"(b)); return d;
}
__device__ __forceinline__ ull fdup(float x) {
    ull d; asm("mov.b64 %0, {%1, %1};" : "=l"(d) : "f"(x)); return d;
}

// ---------------- software grid barrier --------------------------------------
__device__ __forceinline__ void grid_barrier() {
    __syncthreads();
    if (threadIdx.x == 0) {
        __threadfence();
        unsigned long long old = atomicAdd(&g_bar_cnt, 1ULL);
        unsigned long long gen = old / (unsigned long long)NCTA;
        if (old % (unsigned long long)NCTA == (unsigned long long)(NCTA - 1)) {
            *(volatile unsigned long long*)&g_bar_gen = gen + 1ULL;
        } else {
            while (*(volatile unsigned long long*)&g_bar_gen <= gen) { }
            __threadfence();
        }
    }
    __syncthreads();
}

// ---------------- conversion kernels -----------------------------------------
__global__ void convert_x_kernel(const float* __restrict__ x) {
    const int N2 = Bv * Tv * Hv / 2;
    for (int i = blockIdx.x * blockDim.x + threadIdx.x; i < N2; i += gridDim.x * blockDim.x) {
        float2 v = ((const float2*)x)[i];
        __nv_bfloat16 h0 = __float2bfloat16(v.x);
        __nv_bfloat16 h1 = __float2bfloat16(v.y);
        ((__nv_bfloat162*)g_xhi)[i] = __halves2bfloat162(h0, h1);
        ((__nv_bfloat162*)g_xlo)[i] = __halves2bfloat162(
            __float2bfloat16(v.x - __bfloat162float(h0)),
            __float2bfloat16(v.y - __bfloat162float(h1)));
    }
}

__global__ void convert_w_kernel(const float* __restrict__ W,
                                 __nv_bfloat16* __restrict__ hi,
                                 __nv_bfloat16* __restrict__ lo) {
    for (int i = blockIdx.x * blockDim.x + threadIdx.x; i < Hv * FH; i += gridDim.x * blockDim.x) {
        int k = i >> 11, n = i & (FH - 1);
        float v = W[i];
        __nv_bfloat16 h = __float2bfloat16(v);
        hi[n * Hv + k] = h;
        lo[n * Hv + k] = __float2bfloat16(v - __bfloat162float(h));
    }
}

// ---------------- mma.sync split-bf16 GEMM ------------------------------------
// C[32768,2048] = A[32768,512] * Wt[2048,512]^T, 3 passes (hh, hl, lh) kept in
// registers. Tile 128x128, 8 warps (2x4), warp tile 64x32, k-chunk 64.
#define AST 72   /* smem row stride in bf16 (144 B, 16B-aligned, conflict-free) */

__global__ __launch_bounds__(256, 2)
void gemm_mma_kernel(const __nv_bfloat16* __restrict__ whi,
                     const __nv_bfloat16* __restrict__ wlo)
{
    extern __shared__ __nv_bfloat16 smb[];
    __nv_bfloat16* A_s = smb;               // [128][72]
    __nv_bfloat16* B_s = smb + 128 * AST;   // [128][72]

    const int tid = threadIdx.x;
    const int wid = tid >> 5, lane = tid & 31;
    const int bn = blockIdx.x;     // 0..15
    const int bm = blockIdx.y;     // 0..255
    const int wr = wid >> 2;       // 0..1  -> m base wr*64
    const int wc = wid & 3;        // 0..3  -> n base wc*32

    float acc[4][4][4];
#pragma unroll
    for (int mi = 0; mi < 4; ++mi)
#pragma unroll
        for (int nj = 0; nj < 4; ++nj)
#pragma unroll
            for (int r = 0; r < 4; ++r) acc[mi][nj][r] = 0.f;

    // ldmatrix base addresses (k-offset added per k-step)
    uint32_t a_base[4], b_base[2];
    {
        uint32_t As0 = smem_u32(A_s), Bs0 = smem_u32(B_s);
        int arow = (lane & 15);
        int akof = (lane >> 4) * 8;
#pragma unroll
        for (int mi = 0; mi < 4; ++mi)
            a_base[mi] = As0 + ((wr * 64 + mi * 16 + arow) * AST + akof) * 2;
        int brow = (lane & 7) + ((lane >> 4) & 1) * 8;
        int bkof = ((lane >> 3) & 1) * 8;
#pragma unroll
        for (int np = 0; np < 2; ++np)
            b_base[np] = Bs0 + ((wc * 32 + np * 16 + brow) * AST + bkof) * 2;
    }

    const int srow = tid >> 1;            // staging: 128 rows, 2 threads/row
    const int sc8  = (tid & 1) * 4;       // each stores 4 uint4 (32 bf16)

    for (int p = 0; p < 3; ++p) {
        const __nv_bfloat16* Ag = ((p == 2) ? g_xlo : g_xhi) + (size_t)bm * 128 * Hv;
        const __nv_bfloat16* Bg = ((p == 1) ? wlo : whi) + (size_t)bn * 128 * Hv;
        for (int kc = 0; kc < 512; kc += 64) {
            __syncthreads();
#pragma unroll
            for (int u = 0; u < 4; ++u) {
                int c8 = sc8 + u;
                *(uint4*)&A_s[srow * AST + c8 * 8] =
                    *(const uint4*)(Ag + (size_t)srow * Hv + kc + c8 * 8);
                *(uint4*)&B_s[srow * AST + c8 * 8] =
                    *(const uint4*)(Bg + (size_t)srow * Hv + kc + c8 * 8);
            }
            __syncthreads();

#pragma unroll
            for (int ks = 0; ks < 4; ++ks) {
                uint32_t a[4][4], b[2][4];
#pragma unroll
                for (int mi = 0; mi < 4; ++mi)
                    ldsm_x4(a[mi][0], a[mi][1], a[mi][2], a[mi][3],
                            a_base[mi] + ks * 32);
#pragma unroll
                for (int np = 0; np < 2; ++np)
                    ldsm_x4(b[np][0], b[np][1], b[np][2], b[np][3],
                            b_base[np] + ks * 32);
#pragma unroll
                for (int mi = 0; mi < 4; ++mi) {
#pragma unroll
                    for (int nj = 0; nj < 4; ++nj) {
                        uint32_t bf[2] = { b[nj >> 1][(nj & 1) * 2],
                                           b[nj >> 1][(nj & 1) * 2 + 1] };
                        mma16816(acc[mi][nj], a[mi], bf);
                    }
                }
            }
        }
    }

    // Epilogue: write C tile
    const int erow = lane >> 2;
    const int ecol = (lane & 3) * 2;
#pragma unroll
    for (int mi = 0; mi < 4; ++mi) {
#pragma unroll
        for (int nj = 0; nj < 4; ++nj) {
            int row0 = bm * 128 + wr * 64 + mi * 16 + erow;
            int col  = bn * 128 + wc * 32 + nj * 8 + ecol;
            *(float2*)&g_xproj[(size_t)row0 * FH + col] =
                make_float2(acc[mi][nj][0], acc[mi][nj][1]);
            *(float2*)&g_xproj[(size_t)(row0 + 8) * FH + col] =
                make_float2(acc[mi][nj][2], acc[mi][nj][3]);
        }
    }
}

// ---------------- persistent recurrent LSTM layer ----------------------------
__global__ __launch_bounds__(NTHR, 1)
void lstm_layer_kernel(const float* __restrict__ Wh,
                       const float* __restrict__ bvec,
                       const float* __restrict__ h_in,
                       const float* __restrict__ c_in,
                       float* __restrict__ seq_out_ext, int seq_to_internal,
                       float* __restrict__ hT_out,
                       float* __restrict__ cT_out)
{
    extern __shared__ float smemf[];
    float* w_s = smemf;                    // [512][20] (16 used)
    float* h_s = smemf + 512 * 20;         // [512][68] (64 used)
    float* z_s = h_s + 512 * 68;           // [16][68]  z[c][b]
    float* c_s = z_s + 16 * 68;            // [256]

    const float* xp = g_xproj;
    const int tid = threadIdx.x;
    const int n0 = blockIdx.x * 4;

    for (int idx = tid; idx < 512 * 16; idx += NTHR) {
        int k = idx >> 4, cc = idx & 15;
        w_s[k * 20 + cc] = Wh[(size_t)k * FH + (cc >> 2) * Hv + n0 + (cc & 3)];
    }
    if (tid < 256) {
        int b = tid >> 2, j = tid & 3;
        c_s[tid] = c_in[b * Hv + n0 + j];
        __stcg(&g_hT[0][(n0 + j) * Bv + b], h_in[b * Hv + n0 + j]);
    }
    const float bgi = bvec[0] + bvec[1];
    const float bgf = bvec[2] + bvec[3];
    const float bgg = bvec[4] + bvec[5];
    const float bgo = bvec[6] + bvec[7];

    grid_barrier();

    const int tile = tid >> 4;
    const int ksl  = tid & 15;
    const int b0 = (tile >> 2) * 8;
    const int c0 = (tile & 3) * 4;
    const int eb = tid >> 2, ej = tid & 3;

    for (int t = 0; t < Tv; ++t) {
        const float* hsrc = g_hT[t & 1];
        float* hdst = g_hT[(t & 1) ^ 1];

        for (int q = tid; q < (Hv * Bv) / 4; q += NTHR) {
            float4 v = __ldcg((const float4*)hsrc + q);
            int k = q >> 4, bq = q & 15;
            *(float4*)&h_s[k * 68 + bq * 4] = v;
        }
        float x0, x1, x2, x3;
        if (tid < 256) {
            int xbase = (eb * Tv + t) * FH + n0 + ej;
            x0 = xp[xbase];
            x1 = xp[xbase + Hv];
            x2 = xp[xbase + 2 * Hv];
            x3 = xp[xbase + 3 * Hv];
        }
        __syncthreads();

        ull acc[4][4];
#pragma unroll
        for (int bp = 0; bp < 4; ++bp)
#pragma unroll
            for (int cj = 0; cj < 4; ++cj) acc[bp][cj] = 0ULL;

#pragma unroll 4
        for (int i = 0; i < 32; ++i) {
            int k = ksl + (i << 4);
            ulonglong2 h01 = *(const ulonglong2*)&h_s[k * 68 + b0];
            ulonglong2 h23 = *(const ulonglong2*)&h_s[k * 68 + b0 + 4];
            float wv[4];
            *(float4*)&wv[0] = *(const float4*)&w_s[k * 20 + c0];
#pragma unroll
            for (int cj = 0; cj < 4; ++cj) {
                ull wd = fdup(wv[cj]);
                acc[0][cj] = ffma2(h01.x, wd, acc[0][cj]);
                acc[1][cj] = ffma2(h01.y, wd, acc[1][cj]);
                acc[2][cj] = ffma2(h23.x, wd, acc[2][cj]);
                acc[3][cj] = ffma2(h23.y, wd, acc[3][cj]);
            }
        }

#pragma unroll
        for (int m = 8; m >= 1; m >>= 1) {
#pragma unroll
            for (int bp = 0; bp < 4; ++bp)
#pragma unroll
                for (int cj = 0; cj < 4; ++cj) {
                    ull o = __shfl_xor_sync(0xffffffffu, acc[bp][cj], m);
                    acc[bp][cj] = fadd2(acc[bp][cj], o);
                }
        }
        if (ksl < 8) {
            int cj = ksl & 3;
            int bp0 = (ksl >> 2) * 2;
            *(ulonglong2*)&z_s[(c0 + cj) * 68 + b0 + bp0 * 2] =
                make_ulonglong2(acc[bp0][cj], acc[bp0 + 1][cj]);
        }
        __syncthreads();

        if (tid < 256) {
            float zi = z_s[(0  + ej) * 68 + eb] + x0 + bgi;
            float zf = z_s[(4  + ej) * 68 + eb] + x1 + bgf;
            float zg = z_s[(8  + ej) * 68 + eb] + x2 + bgg;
            float zo = z_s[(12 + ej) * 68 + eb] + x3 + bgo;
            float ig = 1.f / (1.f + __expf(-zi));
            float fg = 1.f / (1.f + __expf(-zf));
            float gg = tanhf(zg);
            float og = 1.f / (1.f + __expf(-zo));
            float cn = fmaf(fg, c_s[tid], ig * gg);
            c_s[tid] = cn;
            float hn = og * tanhf(cn);
            __stcg(&hdst[(n0 + ej) * Bv + eb], hn);
            if (seq_to_internal) {
                __nv_bfloat16 hh = __float2bfloat16(hn);
                size_t o = (size_t)(eb * Tv + t) * Hv + n0 + ej;
                g_xhi[o] = hh;
                g_xlo[o] = __float2bfloat16(hn - __bfloat162float(hh));
            } else {
                seq_out_ext[(size_t)(eb * Tv + t) * Hv + n0 + ej] = hn;
            }
            if (t == Tv - 1) {
                hT_out[eb * Hv + n0 + ej] = hn;
                cT_out[eb * Hv + n0 + ej] = cn;
            }
        }
        grid_barrier();
    }
}

// ---------------- launch -----------------------------------------------------
extern "C" void kernel_launch(void* const* d_in, const int* in_sizes, int n_in,
                              void* d_out, int out_size)
{
    const float* x   = (const float*)d_in[0];
    const float* h   = (const float*)d_in[1];
    const float* c   = (const float*)d_in[2];
    const float* Wx0 = (const float*)d_in[3];
    const float* Wh0 = (const float*)d_in[4];
    const float* b0  = (const float*)d_in[5];
    const float* Wx1 = (const float*)d_in[6];
    const float* Wh1 = (const float*)d_in[7];
    const float* b1  = (const float*)d_in[8];
    float* out = (float*)d_out;

    const int LSTM_SMEM = (512 * 20 + 512 * 68 + 16 * 68 + 256) * 4;
    cudaFuncSetAttribute(lstm_layer_kernel,
                         cudaFuncAttributeMaxDynamicSharedMemorySize, LSTM_SMEM);
    const int GEMM_SMEM = 2 * 128 * AST * 2;   // 36864
    cudaFuncSetAttribute(gemm_mma_kernel,
                         cudaFuncAttributeMaxDynamicSharedMemorySize, GEMM_SMEM);

    float* out1 = out;
    float* newh = out + (size_t)Bv * Tv * Hv;
    float* newc = newh + 2 * Bv * Hv;

    __nv_bfloat16 *w0hi, *w0lo, *w1hi, *w1lo;
    cudaGetSymbolAddress((void**)&w0hi, g_w0hi);
    cudaGetSymbolAddress((void**)&w0lo, g_w0lo);
    cudaGetSymbolAddress((void**)&w1hi, g_w1hi);
    cudaGetSymbolAddress((void**)&w1lo, g_w1lo);

    dim3 gg(FH / 128, (Bv * Tv) / 128);   // (16, 256)

    // Weight + input conversion
    convert_w_kernel<<<512, 256>>>(Wx0, w0hi, w0lo);
    convert_w_kernel<<<512, 256>>>(Wx1, w1hi, w1lo);
    convert_x_kernel<<<4096, 256>>>(x);

    // Layer 0
    gemm_mma_kernel<<<gg, 256, GEMM_SMEM>>>(w0hi, w0lo);
    lstm_layer_kernel<<<NCTA, NTHR, LSTM_SMEM>>>(
        Wh0, b0, h, c, nullptr, 1, newh, newc);

    // Layer 1
    gemm_mma_kernel<<<gg, 256, GEMM_SMEM>>>(w1hi, w1lo);
    lstm_layer_kernel<<<NCTA, NTHR, LSTM_SMEM>>>(
        Wh1, b1, h + Bv * Hv, c + Bv * Hv, out1, 0,
        newh + Bv * Hv, newc + Bv * Hv);
}

// round 6
// speedup vs baseline: 1.9589x; 1.0455x over previous
#include <cuda_runtime.h>
#include <cuda_bf16.h>
#include <math.h>
#include <cstdint>

#define Bv 64
#define Tv 512
#define Hv 512
#define FH 2048   /* 4*H */

#define NCTA 128
#define NTHR 512

typedef unsigned long long ull;

// ---------------- device scratch ---------------------------------------------
__device__ float g_xproj[Bv * Tv * FH];            // x-projection for current layer
__device__ __nv_bfloat16 g_xhi[Bv * Tv * Hv];      // GEMM A operand, hi part
__device__ __nv_bfloat16 g_xlo[Bv * Tv * Hv];      // GEMM A operand, lo part
__device__ __nv_bfloat16 g_w0hi[FH * Hv];          // W_x0^T [n][k] hi
__device__ __nv_bfloat16 g_w0lo[FH * Hv];
__device__ __nv_bfloat16 g_w1hi[FH * Hv];          // W_x1^T [n][k] hi
__device__ __nv_bfloat16 g_w1lo[FH * Hv];
__device__ float g_hT[2][Hv * Bv];                 // transposed hidden state [k][b]
__device__ ull g_grp[8 * 16];                      // per-group arrival counters (padded)
__device__ ull g_root = 0ULL;
__device__ ull g_gen = 0ULL;

// ---------------- helpers -----------------------------------------------------
__device__ __forceinline__ uint32_t smem_u32(const void* p) {
    uint32_t a;
    asm("{ .reg .u64 t; cvta.to.shared.u64 t, %1; cvt.u32.u64 %0, t; }" : "=r"(a) : "l"(p));
    return a;
}
__device__ __forceinline__ void cp16(uint32_t dst, const void* src) {
    asm volatile("cp.async.cg.shared.global [%0], [%1], 16;" :: "r"(dst), "l"(src) : "memory");
}
#define CP_COMMIT() asm volatile("cp.async.commit_group;" ::: "memory")
#define CP_WAIT0()  asm volatile("cp.async.wait_group 0;" ::: "memory")
#define CP_WAIT1()  asm volatile("cp.async.wait_group 1;" ::: "memory")

__device__ __forceinline__ void ldsm_x4(uint32_t& r0, uint32_t& r1, uint32_t& r2,
                                        uint32_t& r3, uint32_t addr) {
    asm volatile("ldmatrix.sync.aligned.m8n8.x4.shared.b16 {%0,%1,%2,%3}, [%4];"
                 : "=r"(r0), "=r"(r1), "=r"(r2), "=r"(r3) : "r"(addr));
}
__device__ __forceinline__ void mma16816(float* d, const uint32_t* a, const uint32_t* b) {
    asm volatile(
        "mma.sync.aligned.m16n8k16.row.col.f32.bf16.bf16.f32 "
        "{%0,%1,%2,%3}, {%4,%5,%6,%7}, {%8,%9}, {%0,%1,%2,%3};"
        : "+f"(d[0]), "+f"(d[1]), "+f"(d[2]), "+f"(d[3])
        : "r"(a[0]), "r"(a[1]), "r"(a[2]), "r"(a[3]), "r"(b[0]), "r"(b[1]));
}

// ---------------- packed f32x2 helpers ---------------------------------------
__device__ __forceinline__ ull ffma2(ull a, ull b, ull c) {
    ull d; asm("fma.rn.f32x2 %0, %1, %2, %3;" : "=l"(d) : "l"(a), "l"(b), "l"(c)); return d;
}
__device__ __forceinline__ ull fadd2(ull a, ull b) {
    ull d; asm("add.rn.f32x2 %0, %1, %2;" : "=l"(d) : "l"(a), "l"(b)); return d;
}
__device__ __forceinline__ ull fdup(float x) {
    ull d; asm("mov.b64 %0, {%1, %1};" : "=l"(d) : "f"(x)); return d;
}

// ---------------- hierarchical grid barrier (8 groups x 16 CTAs) -------------
__device__ __forceinline__ void grid_barrier() {
    __syncthreads();
    if (threadIdx.x == 0) {
        __threadfence();
        int g = blockIdx.x >> 4;
        ull o = atomicAdd(&g_grp[g * 16], 1ULL);
        ull s = o >> 4;                       // my generation
        if ((o & 15ULL) == 15ULL) {
            ull r = atomicAdd(&g_root, 1ULL);
            if ((r & 7ULL) == 7ULL) {
                __threadfence();
                *(volatile ull*)&g_gen = (r >> 3) + 1ULL;
            }
        }
        while (*(volatile ull*)&g_gen <= s) { }
        __threadfence();
    }
    __syncthreads();
}

// ---------------- conversion kernels -----------------------------------------
__global__ void convert_x_kernel(const float* __restrict__ x) {
    const int N2 = Bv * Tv * Hv / 2;
    for (int i = blockIdx.x * blockDim.x + threadIdx.x; i < N2; i += gridDim.x * blockDim.x) {
        float2 v = ((const float2*)x)[i];
        __nv_bfloat16 h0 = __float2bfloat16(v.x);
        __nv_bfloat16 h1 = __float2bfloat16(v.y);
        ((__nv_bfloat162*)g_xhi)[i] = __halves2bfloat162(h0, h1);
        ((__nv_bfloat162*)g_xlo)[i] = __halves2bfloat162(
            __float2bfloat16(v.x - __bfloat162float(h0)),
            __float2bfloat16(v.y - __bfloat162float(h1)));
    }
}

__global__ void convert_w_kernel(const float* __restrict__ W,
                                 __nv_bfloat16* __restrict__ hi,
                                 __nv_bfloat16* __restrict__ lo) {
    for (int i = blockIdx.x * blockDim.x + threadIdx.x; i < Hv * FH; i += gridDim.x * blockDim.x) {
        int k = i >> 11, n = i & (FH - 1);
        float v = W[i];
        __nv_bfloat16 h = __float2bfloat16(v);
        hi[n * Hv + k] = h;
        lo[n * Hv + k] = __float2bfloat16(v - __bfloat162float(h));
    }
}

// ---------------- mma.sync split-bf16 GEMM (cp.async double-buffered) --------
#define AST 72   /* smem row stride in bf16 (144 B, 16B-aligned, conflict-free) */
#define GBUFB (128 * AST * 2)  /* bytes per buffer per operand */

__global__ __launch_bounds__(256, 2)
void gemm_mma_kernel(const __nv_bfloat16* __restrict__ whi,
                     const __nv_bfloat16* __restrict__ wlo)
{
    extern __shared__ __nv_bfloat16 smb[];
    const int tid = threadIdx.x;
    const int wid = tid >> 5, lane = tid & 31;
    const int bn = blockIdx.x;
    const int bm = blockIdx.y;
    const int wr = wid >> 2;
    const int wc = wid & 3;

    const uint32_t As0 = smem_u32(smb);
    const uint32_t Bs0 = As0 + 2 * GBUFB;

    float acc[4][4][4];
#pragma unroll
    for (int mi = 0; mi < 4; ++mi)
#pragma unroll
        for (int nj = 0; nj < 4; ++nj)
#pragma unroll
            for (int r = 0; r < 4; ++r) acc[mi][nj][r] = 0.f;

    uint32_t a_base[4], b_base[2];
    {
        int arow = (lane & 15);
        int akof = (lane >> 4) * 8;
#pragma unroll
        for (int mi = 0; mi < 4; ++mi)
            a_base[mi] = As0 + ((wr * 64 + mi * 16 + arow) * AST + akof) * 2;
        int brow = (lane & 7) + ((lane >> 4) & 1) * 8;
        int bkof = ((lane >> 3) & 1) * 8;
#pragma unroll
        for (int np = 0; np < 2; ++np)
            b_base[np] = Bs0 + ((wc * 32 + np * 16 + brow) * AST + bkof) * 2;
    }

    const int sr = tid >> 1;
    const int sh = (tid & 1) * 32;

    // stage chunk c into buffer buf
    auto do_stage = [&](int c, int buf) {
        int p = c >> 3, kc = (c & 7) * 64;
        const __nv_bfloat16* Ag = ((p == 2) ? g_xlo : g_xhi) + (size_t)bm * 128 * Hv;
        const __nv_bfloat16* Bg = ((p == 1) ? wlo : whi) + (size_t)bn * 128 * Hv;
#pragma unroll
        for (int u = 0; u < 4; ++u) {
            int co = sh + u * 8;
            cp16(As0 + buf * GBUFB + (sr * AST + co) * 2, Ag + (size_t)sr * Hv + kc + co);
            cp16(Bs0 + buf * GBUFB + (sr * AST + co) * 2, Bg + (size_t)sr * Hv + kc + co);
        }
        CP_COMMIT();
    };

    do_stage(0, 0);
    for (int c = 0; c < 24; ++c) {
        int buf = c & 1;
        if (c + 1 < 24) { do_stage(c + 1, buf ^ 1); CP_WAIT1(); }
        else            { CP_WAIT0(); }
        __syncthreads();
        uint32_t bo = buf * GBUFB;
#pragma unroll
        for (int ks = 0; ks < 4; ++ks) {
            uint32_t a[4][4], b[2][4];
#pragma unroll
            for (int mi = 0; mi < 4; ++mi)
                ldsm_x4(a[mi][0], a[mi][1], a[mi][2], a[mi][3], a_base[mi] + bo + ks * 32);
#pragma unroll
            for (int np = 0; np < 2; ++np)
                ldsm_x4(b[np][0], b[np][1], b[np][2], b[np][3], b_base[np] + bo + ks * 32);
#pragma unroll
            for (int mi = 0; mi < 4; ++mi) {
#pragma unroll
                for (int nj = 0; nj < 4; ++nj) {
                    uint32_t bf[2] = { b[nj >> 1][(nj & 1) * 2],
                                       b[nj >> 1][(nj & 1) * 2 + 1] };
                    mma16816(acc[mi][nj], a[mi], bf);
                }
            }
        }
        __syncthreads();
    }

    const int erow = lane >> 2;
    const int ecol = (lane & 3) * 2;
#pragma unroll
    for (int mi = 0; mi < 4; ++mi) {
#pragma unroll
        for (int nj = 0; nj < 4; ++nj) {
            int row0 = bm * 128 + wr * 64 + mi * 16 + erow;
            int col  = bn * 128 + wc * 32 + nj * 8 + ecol;
            *(float2*)&g_xproj[(size_t)row0 * FH + col] =
                make_float2(acc[mi][nj][0], acc[mi][nj][1]);
            *(float2*)&g_xproj[(size_t)(row0 + 8) * FH + col] =
                make_float2(acc[mi][nj][2], acc[mi][nj][3]);
        }
    }
}

// ---------------- persistent recurrent LSTM layer ----------------------------
// 128 CTAs x 512 threads. Warp = one (8b x 8c) tile, lanes = 32 k-slices of 16.
// cp.async 2-phase h staging overlapped with compute; reduce-scatter butterfly;
// hierarchical grid barrier per step.
__global__ __launch_bounds__(NTHR, 1)
void lstm_layer_kernel(const float* __restrict__ Wh,
                       const float* __restrict__ bvec,
                       const float* __restrict__ h_in,
                       const float* __restrict__ c_in,
                       float* __restrict__ seq_out_ext, int seq_to_internal,
                       float* __restrict__ hT_out,
                       float* __restrict__ cT_out)
{
    extern __shared__ float smemf[];
    float* w_s = smemf;                    // [512][20] (16 used)
    float* h_s = smemf + 512 * 20;         // [512][68] (64 used)
    float* z_s = h_s + 512 * 68;           // [16][68]  z[c][b]
    float* c_s = z_s + 16 * 68;            // [256]

    const float* xp = g_xproj;
    const int tid = threadIdx.x;
    const int n0 = blockIdx.x * 4;
    const uint32_t hs_u32 = smem_u32(h_s);

    for (int idx = tid; idx < 512 * 16; idx += NTHR) {
        int k = idx >> 4, cc = idx & 15;
        w_s[k * 20 + cc] = Wh[(size_t)k * FH + (cc >> 2) * Hv + n0 + (cc & 3)];
    }
    if (tid < 256) {
        int b = tid >> 2, j = tid & 3;
        c_s[tid] = c_in[b * Hv + n0 + j];
        __stcg(&g_hT[0][(n0 + j) * Bv + b], h_in[b * Hv + n0 + j]);
    }
    const float bgi = bvec[0] + bvec[1];
    const float bgf = bvec[2] + bvec[3];
    const float bgg = bvec[4] + bvec[5];
    const float bgo = bvec[6] + bvec[7];

    grid_barrier();

    const int tile = tid >> 5;             // warp id 0..15
    const int ksl  = tid & 31;             // k-slice 0..31
    const int b0 = (tile >> 1) * 8;        // 8 batches
    const int c0 = (tile & 1) * 8;         // 8 cols
    const int eb = tid >> 2, ej = tid & 3; // epilogue mapping (tid<256)

    for (int t = 0; t < Tv; ++t) {
        const float* hsrc = g_hT[t & 1];
        float* hdst = g_hT[(t & 1) ^ 1];

        // issue 2-phase h staging (cp.async, no regs)
#pragma unroll
        for (int u = 0; u < 8; ++u) {
            int idx = tid + u * 512;                       // k < 256
            cp16(hs_u32 + ((idx >> 4) * 68 + (idx & 15) * 4) * 4,
                 (const char*)hsrc + (size_t)idx * 16);
        }
        CP_COMMIT();
#pragma unroll
        for (int u = 0; u < 8; ++u) {
            int idx = 4096 + tid + u * 512;                // k >= 256
            cp16(hs_u32 + ((idx >> 4) * 68 + (idx & 15) * 4) * 4,
                 (const char*)hsrc + (size_t)idx * 16);
        }
        CP_COMMIT();

        // prefetch x-projection for the epilogue
        float x0, x1, x2, x3;
        if (tid < 256) {
            int xbase = (eb * Tv + t) * FH + n0 + ej;
            x0 = xp[xbase];
            x1 = xp[xbase + Hv];
            x2 = xp[xbase + 2 * Hv];
            x3 = xp[xbase + 3 * Hv];
        }

        ull acc[32];
#pragma unroll
        for (int q = 0; q < 32; ++q) acc[q] = 0ULL;

        CP_WAIT1();
        __syncthreads();
        // phase A: k in [0,256)
#pragma unroll 4
        for (int i = 0; i < 8; ++i) {
            int k = ksl + (i << 5);
            ulonglong2 h01 = *(const ulonglong2*)&h_s[k * 68 + b0];
            ulonglong2 h23 = *(const ulonglong2*)&h_s[k * 68 + b0 + 4];
            ull hp[4] = { h01.x, h01.y, h23.x, h23.y };
            float wv[8];
            *(float4*)&wv[0] = *(const float4*)&w_s[k * 20 + c0];
            *(float4*)&wv[4] = *(const float4*)&w_s[k * 20 + c0 + 4];
#pragma unroll
            for (int cj = 0; cj < 8; ++cj) {
                ull wd = fdup(wv[cj]);
#pragma unroll
                for (int bp = 0; bp < 4; ++bp)
                    acc[bp * 8 + cj] = ffma2(hp[bp], wd, acc[bp * 8 + cj]);
            }
        }
        CP_WAIT0();
        __syncthreads();
        // phase B: k in [256,512)
#pragma unroll 4
        for (int i = 8; i < 16; ++i) {
            int k = ksl + (i << 5);
            ulonglong2 h01 = *(const ulonglong2*)&h_s[k * 68 + b0];
            ulonglong2 h23 = *(const ulonglong2*)&h_s[k * 68 + b0 + 4];
            ull hp[4] = { h01.x, h01.y, h23.x, h23.y };
            float wv[8];
            *(float4*)&wv[0] = *(const float4*)&w_s[k * 20 + c0];
            *(float4*)&wv[4] = *(const float4*)&w_s[k * 20 + c0 + 4];
#pragma unroll
            for (int cj = 0; cj < 8; ++cj) {
                ull wd = fdup(wv[cj]);
#pragma unroll
                for (int bp = 0; bp < 4; ++bp)
                    acc[bp * 8 + cj] = ffma2(hp[bp], wd, acc[bp * 8 + cj]);
            }
        }

        // reduce-scatter butterfly over 32 lanes: lane ksl ends owning flat
        // element q = ksl (bp = ksl>>3, cj = ksl&7), fully reduced.
#pragma unroll
        for (int m = 16; m >= 1; m >>= 1) {
            bool hi = (ksl & m) != 0;
#pragma unroll
            for (int j = 0; j < m; ++j) {
                ull keep = hi ? acc[j + m] : acc[j];
                ull send = hi ? acc[j] : acc[j + m];
                ull o = __shfl_xor_sync(0xffffffffu, send, m);
                acc[j] = fadd2(keep, o);
            }
        }
        {
            int bp = ksl >> 3, cj = ksl & 7;
            *(ull*)&z_s[(c0 + cj) * 68 + b0 + 2 * bp] = acc[0];
        }
        __syncthreads();

        // gate epilogue: thread -> (b=eb, j=ej)
        if (tid < 256) {
            float zi = z_s[(0  + ej) * 68 + eb] + x0 + bgi;
            float zf = z_s[(4  + ej) * 68 + eb] + x1 + bgf;
            float zg = z_s[(8  + ej) * 68 + eb] + x2 + bgg;
            float zo = z_s[(12 + ej) * 68 + eb] + x3 + bgo;
            float ig = 1.f / (1.f + __expf(-zi));
            float fg = 1.f / (1.f + __expf(-zf));
            float gg = tanhf(zg);
            float og = 1.f / (1.f + __expf(-zo));
            float cn = fmaf(fg, c_s[tid], ig * gg);
            c_s[tid] = cn;
            float hn = og * tanhf(cn);
            __stcg(&hdst[(n0 + ej) * Bv + eb], hn);
            if (seq_to_internal) {
                __nv_bfloat16 hh = __float2bfloat16(hn);
                size_t o = (size_t)(eb * Tv + t) * Hv + n0 + ej;
                g_xhi[o] = hh;
                g_xlo[o] = __float2bfloat16(hn - __bfloat162float(hh));
            } else {
                seq_out_ext[(size_t)(eb * Tv + t) * Hv + n0 + ej] = hn;
            }
            if (t == Tv - 1) {
                hT_out[eb * Hv + n0 + ej] = hn;
                cT_out[eb * Hv + n0 + ej] = cn;
            }
        }
        grid_barrier();
    }
}

// ---------------- launch -----------------------------------------------------
extern "C" void kernel_launch(void* const* d_in, const int* in_sizes, int n_in,
                              void* d_out, int out_size)
{
    const float* x   = (const float*)d_in[0];
    const float* h   = (const float*)d_in[1];
    const float* c   = (const float*)d_in[2];
    const float* Wx0 = (const float*)d_in[3];
    const float* Wh0 = (const float*)d_in[4];
    const float* b0  = (const float*)d_in[5];
    const float* Wx1 = (const float*)d_in[6];
    const float* Wh1 = (const float*)d_in[7];
    const float* b1  = (const float*)d_in[8];
    float* out = (float*)d_out;

    const int LSTM_SMEM = (512 * 20 + 512 * 68 + 16 * 68 + 256) * 4;
    cudaFuncSetAttribute(lstm_layer_kernel,
                         cudaFuncAttributeMaxDynamicSharedMemorySize, LSTM_SMEM);
    const int GEMM_SMEM = 4 * GBUFB;   // 73728
    cudaFuncSetAttribute(gemm_mma_kernel,
                         cudaFuncAttributeMaxDynamicSharedMemorySize, GEMM_SMEM);

    float* out1 = out;
    float* newh = out + (size_t)Bv * Tv * Hv;
    float* newc = newh + 2 * Bv * Hv;

    __nv_bfloat16 *w0hi, *w0lo, *w1hi, *w1lo;
    cudaGetSymbolAddress((void**)&w0hi, g_w0hi);
    cudaGetSymbolAddress((void**)&w0lo, g_w0lo);
    cudaGetSymbolAddress((void**)&w1hi, g_w1hi);
    cudaGetSymbolAddress((void**)&w1lo, g_w1lo);

    dim3 gg(FH / 128, (Bv * Tv) / 128);   // (16, 256)

    convert_w_kernel<<<512, 256>>>(Wx0, w0hi, w0lo);
    convert_w_kernel<<<512, 256>>>(Wx1, w1hi, w1lo);
    convert_x_kernel<<<4096, 256>>>(x);

    // Layer 0
    gemm_mma_kernel<<<gg, 256, GEMM_SMEM>>>(w0hi, w0lo);
    lstm_layer_kernel<<<NCTA, NTHR, LSTM_SMEM>>>(
        Wh0, b0, h, c, nullptr, 1, newh, newc);

    // Layer 1
    gemm_mma_kernel<<<gg, 256, GEMM_SMEM>>>(w1hi, w1lo);
    lstm_layer_kernel<<<NCTA, NTHR, LSTM_SMEM>>>(
        Wh1, b1, h + Bv * Hv, c + Bv * Hv, out1, 0,
        newh + Bv * Hv, newc + Bv * Hv);
}

// round 7
// speedup vs baseline: 2.2586x; 1.1530x over previous
#include <cuda_runtime.h>
#include <cuda_bf16.h>
#include <math.h>
#include <cstdint>

#define Bv 64
#define Tv 512
#define Hv 512
#define FH 2048   /* 4*H */

#define NCTA 128
#define NTHR 512

typedef unsigned long long ull;

// ---------------- device scratch ---------------------------------------------
__device__ float g_xproj[Bv * Tv * FH];            // x-projection for current layer
__device__ __nv_bfloat16 g_xhi[Bv * Tv * Hv];      // GEMM A operand, hi part
__device__ __nv_bfloat16 g_xlo[Bv * Tv * Hv];      // GEMM A operand, lo part
__device__ __nv_bfloat16 g_w0hi[FH * Hv];          // W_x0^T [n][k] hi
__device__ __nv_bfloat16 g_w0lo[FH * Hv];
__device__ __nv_bfloat16 g_w1hi[FH * Hv];          // W_x1^T [n][k] hi
__device__ __nv_bfloat16 g_w1lo[FH * Hv];
__device__ float g_hT[2][Hv * Bv];                 // transposed hidden state [k][b]
__device__ ull g_grp[16 * 16];                     // per-group arrival counters (padded)
__device__ ull g_root = 0ULL;
__device__ ull g_gen = 0ULL;

// ---------------- helpers -----------------------------------------------------
__device__ __forceinline__ uint32_t smem_u32(const void* p) {
    uint32_t a;
    asm("{ .reg .u64 t; cvta.to.shared.u64 t, %1; cvt.u32.u64 %0, t; }" : "=r"(a) : "l"(p));
    return a;
}
__device__ __forceinline__ void cp16(uint32_t dst, const void* src) {
    asm volatile("cp.async.cg.shared.global [%0], [%1], 16;" :: "r"(dst), "l"(src) : "memory");
}
#define CP_COMMIT() asm volatile("cp.async.commit_group;" ::: "memory")
#define CP_WAIT0()  asm volatile("cp.async.wait_group 0;" ::: "memory")
#define CP_WAIT1()  asm volatile("cp.async.wait_group 1;" ::: "memory")

__device__ __forceinline__ void ldsm_x4(uint32_t& r0, uint32_t& r1, uint32_t& r2,
                                        uint32_t& r3, uint32_t addr) {
    asm volatile("ldmatrix.sync.aligned.m8n8.x4.shared.b16 {%0,%1,%2,%3}, [%4];"
                 : "=r"(r0), "=r"(r1), "=r"(r2), "=r"(r3) : "r"(addr));
}
__device__ __forceinline__ void mma16816(float* d, const uint32_t* a, const uint32_t* b) {
    asm volatile(
        "mma.sync.aligned.m16n8k16.row.col.f32.bf16.bf16.f32 "
        "{%0,%1,%2,%3}, {%4,%5,%6,%7}, {%8,%9}, {%0,%1,%2,%3};"
        : "+f"(d[0]), "+f"(d[1]), "+f"(d[2]), "+f"(d[3])
        : "r"(a[0]), "r"(a[1]), "r"(a[2]), "r"(a[3]), "r"(b[0]), "r"(b[1]));
}

// ---------------- packed f32x2 helpers ---------------------------------------
__device__ __forceinline__ ull ffma2(ull a, ull b, ull c) {
    ull d; asm("fma.rn.f32x2 %0, %1, %2, %3;" : "=l"(d) : "l"(a), "l"(b), "l"(c)); return d;
}
__device__ __forceinline__ ull fadd2(ull a, ull b) {
    ull d; asm("add.rn.f32x2 %0, %1, %2;" : "=l"(d) : "l"(a), "l"(b)); return d;
}
__device__ __forceinline__ ull fdup(float x) {
    ull d; asm("mov.b64 %0, {%1, %1};" : "=l"(d) : "f"(x)); return d;
}

// ---------------- hierarchical grid barrier (16 groups x 8 CTAs) -------------
__device__ __forceinline__ void grid_barrier() {
    __syncthreads();
    if (threadIdx.x == 0) {
        __threadfence();
        int g = blockIdx.x >> 3;
        ull o = atomicAdd(&g_grp[g * 16], 1ULL);
        ull s = o >> 3;                       // my generation
        if ((o & 7ULL) == 7ULL) {
            ull r = atomicAdd(&g_root, 1ULL);
            if ((r & 15ULL) == 15ULL) {
                __threadfence();
                *(volatile ull*)&g_gen = (r >> 4) + 1ULL;
            }
        }
        while (*(volatile ull*)&g_gen <= s) { }
        __threadfence();
    }
    __syncthreads();
}

// ---------------- conversion kernels -----------------------------------------
__global__ void convert_x_kernel(const float* __restrict__ x) {
    const int N2 = Bv * Tv * Hv / 2;
    for (int i = blockIdx.x * blockDim.x + threadIdx.x; i < N2; i += gridDim.x * blockDim.x) {
        float2 v = ((const float2*)x)[i];
        __nv_bfloat16 h0 = __float2bfloat16(v.x);
        __nv_bfloat16 h1 = __float2bfloat16(v.y);
        ((__nv_bfloat162*)g_xhi)[i] = __halves2bfloat162(h0, h1);
        ((__nv_bfloat162*)g_xlo)[i] = __halves2bfloat162(
            __float2bfloat16(v.x - __bfloat162float(h0)),
            __float2bfloat16(v.y - __bfloat162float(h1)));
    }
}

__global__ void convert_w_kernel(const float* __restrict__ W,
                                 __nv_bfloat16* __restrict__ hi,
                                 __nv_bfloat16* __restrict__ lo) {
    for (int i = blockIdx.x * blockDim.x + threadIdx.x; i < Hv * FH; i += gridDim.x * blockDim.x) {
        int k = i >> 11, n = i & (FH - 1);
        float v = W[i];
        __nv_bfloat16 h = __float2bfloat16(v);
        hi[n * Hv + k] = h;
        lo[n * Hv + k] = __float2bfloat16(v - __bfloat162float(h));
    }
}

// ---------------- mma.sync split-bf16 GEMM (3-stage cp.async pipeline) -------
#define AST 72   /* smem row stride in bf16 (144 B, 16B-aligned, conflict-free) */
#define GBUFB (128 * AST * 2)  /* bytes per buffer per operand */

__global__ __launch_bounds__(256, 2)
void gemm_mma_kernel(const __nv_bfloat16* __restrict__ whi,
                     const __nv_bfloat16* __restrict__ wlo)
{
    extern __shared__ __nv_bfloat16 smb[];
    const int tid = threadIdx.x;
    const int wid = tid >> 5, lane = tid & 31;
    const int bn = blockIdx.x;
    const int bm = blockIdx.y;
    const int wr = wid >> 2;
    const int wc = wid & 3;

    const uint32_t As0 = smem_u32(smb);
    const uint32_t Bs0 = As0 + 3 * GBUFB;

    float acc[4][4][4];
#pragma unroll
    for (int mi = 0; mi < 4; ++mi)
#pragma unroll
        for (int nj = 0; nj < 4; ++nj)
#pragma unroll
            for (int r = 0; r < 4; ++r) acc[mi][nj][r] = 0.f;

    uint32_t a_base[4], b_base[2];
    {
        int arow = (lane & 15);
        int akof = (lane >> 4) * 8;
#pragma unroll
        for (int mi = 0; mi < 4; ++mi)
            a_base[mi] = As0 + ((wr * 64 + mi * 16 + arow) * AST + akof) * 2;
        int brow = (lane & 7) + ((lane >> 4) & 1) * 8;
        int bkof = ((lane >> 3) & 1) * 8;
#pragma unroll
        for (int np = 0; np < 2; ++np)
            b_base[np] = Bs0 + ((wc * 32 + np * 16 + brow) * AST + bkof) * 2;
    }

    const int sr = tid >> 1;
    const int sh = (tid & 1) * 32;

    auto do_stage = [&](int c, int buf) {
        int p = c >> 3, kc = (c & 7) * 64;
        const __nv_bfloat16* Ag = ((p == 2) ? g_xlo : g_xhi) + (size_t)bm * 128 * Hv;
        const __nv_bfloat16* Bg = ((p == 1) ? wlo : whi) + (size_t)bn * 128 * Hv;
#pragma unroll
        for (int u = 0; u < 4; ++u) {
            int co = sh + u * 8;
            cp16(As0 + buf * GBUFB + (sr * AST + co) * 2, Ag + (size_t)sr * Hv + kc + co);
            cp16(Bs0 + buf * GBUFB + (sr * AST + co) * 2, Bg + (size_t)sr * Hv + kc + co);
        }
        CP_COMMIT();
    };

    do_stage(0, 0);
    do_stage(1, 1);
    for (int c = 0; c < 24; ++c) {
        if (c + 1 < 24) CP_WAIT1(); else CP_WAIT0();
        __syncthreads();
        uint32_t bo = (uint32_t)(c % 3) * GBUFB;
#pragma unroll
        for (int ks = 0; ks < 4; ++ks) {
            uint32_t a[4][4], b[2][4];
#pragma unroll
            for (int mi = 0; mi < 4; ++mi)
                ldsm_x4(a[mi][0], a[mi][1], a[mi][2], a[mi][3], a_base[mi] + bo + ks * 32);
#pragma unroll
            for (int np = 0; np < 2; ++np)
                ldsm_x4(b[np][0], b[np][1], b[np][2], b[np][3], b_base[np] + bo + ks * 32);
#pragma unroll
            for (int mi = 0; mi < 4; ++mi) {
#pragma unroll
                for (int nj = 0; nj < 4; ++nj) {
                    uint32_t bf[2] = { b[nj >> 1][(nj & 1) * 2],
                                       b[nj >> 1][(nj & 1) * 2 + 1] };
                    mma16816(acc[mi][nj], a[mi], bf);
                }
            }
        }
        if (c + 2 < 24) do_stage(c + 2, (c + 2) % 3);
    }

    const int erow = lane >> 2;
    const int ecol = (lane & 3) * 2;
#pragma unroll
    for (int mi = 0; mi < 4; ++mi) {
#pragma unroll
        for (int nj = 0; nj < 4; ++nj) {
            int row0 = bm * 128 + wr * 64 + mi * 16 + erow;
            int col  = bn * 128 + wc * 32 + nj * 8 + ecol;
            *(float2*)&g_xproj[(size_t)row0 * FH + col] =
                make_float2(acc[mi][nj][0], acc[mi][nj][1]);
            *(float2*)&g_xproj[(size_t)(row0 + 8) * FH + col] =
                make_float2(acc[mi][nj][2], acc[mi][nj][3]);
        }
    }
}

// ---------------- persistent recurrent LSTM layer ----------------------------
// 128 CTAs = 32 col-groups x 4 batch-groups. CTA owns 16 h-cols (64 z-cols,
// Wh slice 128KB in smem, loaded once) x 16 batches (h slice only 32KB/step).
// Warp = 8 z-cols x 8 batches tile, lanes = 32 k-slices; reduce-scatter.
__global__ __launch_bounds__(NTHR, 1)
void lstm_layer_kernel(const float* __restrict__ Wh,
                       const float* __restrict__ bvec,
                       const float* __restrict__ h_in,
                       const float* __restrict__ c_in,
                       float* __restrict__ seq_out_ext, int seq_to_internal,
                       float* __restrict__ hT_out,
                       float* __restrict__ cT_out)
{
    extern __shared__ float smemf[];
    float* w_s = smemf;                    // [512][68] (64 z-cols used)
    float* h_s = smemf + 512 * 68;         // [512][20] (16 batches used)
    float* z_s = h_s + 512 * 20;           // [64][20]  z[c][b]
    float* c_s = z_s + 64 * 20;            // [256]

    const float* xp = g_xproj;
    const int tid = threadIdx.x;
    const int cg = blockIdx.x & 31;        // col group
    const int bg = blockIdx.x >> 5;        // batch group
    const int n0 = cg * 16;                // base hidden column
    const int bb0 = bg * 16;               // base batch
    const uint32_t hs_u32 = smem_u32(h_s);

    // Wh slice: w_s[k*68 + gate*16 + j] = Wh[k][gate*512 + n0 + j], float4 loads
    for (int idx = tid; idx < 512 * 16; idx += NTHR) {
        int k = idx >> 4, q = idx & 15;
        int gate = q >> 2, j4 = (q & 3) * 4;
        *(float4*)&w_s[k * 68 + gate * 16 + j4] =
            *(const float4*)&Wh[(size_t)k * FH + gate * Hv + n0 + j4];
    }
    // c state + transposed h seed (b = tid>>4, j = tid&15)
    if (tid < 256) {
        int b = tid >> 4, j = tid & 15;
        c_s[tid] = c_in[(bb0 + b) * Hv + n0 + j];
        __stcg(&g_hT[0][(n0 + j) * Bv + bb0 + b], h_in[(bb0 + b) * Hv + n0 + j]);
    }
    const float bgi = bvec[0] + bvec[1];
    const float bgf = bvec[2] + bvec[3];
    const float bgg = bvec[4] + bvec[5];
    const float bgo = bvec[6] + bvec[7];

    grid_barrier();

    const int tile = tid >> 5;              // warp 0..15
    const int ksl  = tid & 31;              // k-slice 0..31
    const int c0 = (tile & 7) * 8;          // 8 z-cols
    const int b0 = (tile >> 3) * 8;         // 8 batches (local)
    const int eb = tid >> 4, ej = tid & 15; // epilogue mapping (tid<256)

    for (int t = 0; t < Tv; ++t) {
        const float* hsrc = g_hT[t & 1];
        float* hdst = g_hT[(t & 1) ^ 1];

        // stage h slice [512 k][16 b] (32KB), 2-phase cp.async
#pragma unroll
        for (int u = 0; u < 2; ++u) {
            int f = tid + u * 512;                  // k = f>>2 < 256
            cp16(hs_u32 + ((f >> 2) * 20 + (f & 3) * 4) * 4,
                 hsrc + (f >> 2) * Bv + bb0 + (f & 3) * 4);
        }
        CP_COMMIT();
#pragma unroll
        for (int u = 2; u < 4; ++u) {
            int f = tid + u * 512;
            cp16(hs_u32 + ((f >> 2) * 20 + (f & 3) * 4) * 4,
                 hsrc + (f >> 2) * Bv + bb0 + (f & 3) * 4);
        }
        CP_COMMIT();

        // prefetch x-projection for the epilogue
        float x0, x1, x2, x3;
        if (tid < 256) {
            int xbase = ((bb0 + eb) * Tv + t) * FH + n0 + ej;
            x0 = xp[xbase];
            x1 = xp[xbase + Hv];
            x2 = xp[xbase + 2 * Hv];
            x3 = xp[xbase + 3 * Hv];
        }

        ull acc[32];
#pragma unroll
        for (int q = 0; q < 32; ++q) acc[q] = 0ULL;

        CP_WAIT1();
        __syncthreads();
        // phase A: k in [0,256)
#pragma unroll 4
        for (int i = 0; i < 8; ++i) {
            int k = ksl + (i << 5);
            ulonglong2 h01 = *(const ulonglong2*)&h_s[k * 20 + b0];
            ulonglong2 h23 = *(const ulonglong2*)&h_s[k * 20 + b0 + 4];
            ull hp[4] = { h01.x, h01.y, h23.x, h23.y };
            float wv[8];
            *(float4*)&wv[0] = *(const float4*)&w_s[k * 68 + c0];
            *(float4*)&wv[4] = *(const float4*)&w_s[k * 68 + c0 + 4];
#pragma unroll
            for (int cj = 0; cj < 8; ++cj) {
                ull wd = fdup(wv[cj]);
#pragma unroll
                for (int bp = 0; bp < 4; ++bp)
                    acc[bp * 8 + cj] = ffma2(hp[bp], wd, acc[bp * 8 + cj]);
            }
        }
        CP_WAIT0();
        __syncthreads();
        // phase B: k in [256,512)
#pragma unroll 4
        for (int i = 8; i < 16; ++i) {
            int k = ksl + (i << 5);
            ulonglong2 h01 = *(const ulonglong2*)&h_s[k * 20 + b0];
            ulonglong2 h23 = *(const ulonglong2*)&h_s[k * 20 + b0 + 4];
            ull hp[4] = { h01.x, h01.y, h23.x, h23.y };
            float wv[8];
            *(float4*)&wv[0] = *(const float4*)&w_s[k * 68 + c0];
            *(float4*)&wv[4] = *(const float4*)&w_s[k * 68 + c0 + 4];
#pragma unroll
            for (int cj = 0; cj < 8; ++cj) {
                ull wd = fdup(wv[cj]);
#pragma unroll
                for (int bp = 0; bp < 4; ++bp)
                    acc[bp * 8 + cj] = ffma2(hp[bp], wd, acc[bp * 8 + cj]);
            }
        }

        // reduce-scatter butterfly: lane ksl ends owning (bp=ksl>>3, cj=ksl&7)
#pragma unroll
        for (int m = 16; m >= 1; m >>= 1) {
            bool hi = (ksl & m) != 0;
#pragma unroll
            for (int j = 0; j < m; ++j) {
                ull keep = hi ? acc[j + m] : acc[j];
                ull send = hi ? acc[j] : acc[j + m];
                ull o = __shfl_xor_sync(0xffffffffu, send, m);
                acc[j] = fadd2(keep, o);
            }
        }
        {
            int bp = ksl >> 3, cj = ksl & 7;
            *(ull*)&z_s[(c0 + cj) * 20 + b0 + 2 * bp] = acc[0];
        }
        __syncthreads();

        // gate epilogue: thread -> (local batch eb, col offset ej)
        if (tid < 256) {
            float zi = z_s[(0  + ej) * 20 + eb] + x0 + bgi;
            float zf = z_s[(16 + ej) * 20 + eb] + x1 + bgf;
            float zg = z_s[(32 + ej) * 20 + eb] + x2 + bgg;
            float zo = z_s[(48 + ej) * 20 + eb] + x3 + bgo;
            float ig = 1.f / (1.f + __expf(-zi));
            float fg = 1.f / (1.f + __expf(-zf));
            float gg = tanhf(zg);
            float og = 1.f / (1.f + __expf(-zo));
            float cn = fmaf(fg, c_s[tid], ig * gg);
            c_s[tid] = cn;
            float hn = og * tanhf(cn);
            __stcg(&hdst[(n0 + ej) * Bv + bb0 + eb], hn);
            size_t o = (size_t)((bb0 + eb) * Tv + t) * Hv + n0 + ej;
            if (seq_to_internal) {
                __nv_bfloat16 hh = __float2bfloat16(hn);
                g_xhi[o] = hh;
                g_xlo[o] = __float2bfloat16(hn - __bfloat162float(hh));
            } else {
                seq_out_ext[o] = hn;
            }
            if (t == Tv - 1) {
                hT_out[(bb0 + eb) * Hv + n0 + ej] = hn;
                cT_out[(bb0 + eb) * Hv + n0 + ej] = cn;
            }
        }
        grid_barrier();
    }
}

// ---------------- launch -----------------------------------------------------
extern "C" void kernel_launch(void* const* d_in, const int* in_sizes, int n_in,
                              void* d_out, int out_size)
{
    const float* x   = (const float*)d_in[0];
    const float* h   = (const float*)d_in[1];
    const float* c   = (const float*)d_in[2];
    const float* Wx0 = (const float*)d_in[3];
    const float* Wh0 = (const float*)d_in[4];
    const float* b0  = (const float*)d_in[5];
    const float* Wx1 = (const float*)d_in[6];
    const float* Wh1 = (const float*)d_in[7];
    const float* b1  = (const float*)d_in[8];
    float* out = (float*)d_out;

    const int LSTM_SMEM = (512 * 68 + 512 * 20 + 64 * 20 + 256) * 4;  // 186368
    cudaFuncSetAttribute(lstm_layer_kernel,
                         cudaFuncAttributeMaxDynamicSharedMemorySize, LSTM_SMEM);
    const int GEMM_SMEM = 6 * GBUFB;   // 110592
    cudaFuncSetAttribute(gemm_mma_kernel,
                         cudaFuncAttributeMaxDynamicSharedMemorySize, GEMM_SMEM);

    float* out1 = out;
    float* newh = out + (size_t)Bv * Tv * Hv;
    float* newc = newh + 2 * Bv * Hv;

    __nv_bfloat16 *w0hi, *w0lo, *w1hi, *w1lo;
    cudaGetSymbolAddress((void**)&w0hi, g_w0hi);
    cudaGetSymbolAddress((void**)&w0lo, g_w0lo);
    cudaGetSymbolAddress((void**)&w1hi, g_w1hi);
    cudaGetSymbolAddress((void**)&w1lo, g_w1lo);

    dim3 gg(FH / 128, (Bv * Tv) / 128);   // (16, 256)

    convert_w_kernel<<<512, 256>>>(Wx0, w0hi, w0lo);
    convert_w_kernel<<<512, 256>>>(Wx1, w1hi, w1lo);
    convert_x_kernel<<<4096, 256>>>(x);

    // Layer 0
    gemm_mma_kernel<<<gg, 256, GEMM_SMEM>>>(w0hi, w0lo);
    lstm_layer_kernel<<<NCTA, NTHR, LSTM_SMEM>>>(
        Wh0, b0, h, c, nullptr, 1, newh, newc);

    // Layer 1
    gemm_mma_kernel<<<gg, 256, GEMM_SMEM>>>(w1hi, w1lo);
    lstm_layer_kernel<<<NCTA, NTHR, LSTM_SMEM>>>(
        Wh1, b1, h + Bv * Hv, c + Bv * Hv, out1, 0,
        newh + Bv * Hv, newc + Bv * Hv);
}

// round 8
// speedup vs baseline: 2.3899x; 1.0581x over previous
#include <cuda_runtime.h>
#include <cuda_bf16.h>
#include <math.h>
#include <cstdint>

#define Bv 64
#define Tv 512
#define Hv 512
#define FH 2048   /* 4*H */

#define NCTA 128
#define NTHR 512

typedef unsigned long long ull;

// ---------------- device scratch ---------------------------------------------
__device__ float g_xproj[Bv * Tv * FH];            // x-projection for current layer
__device__ __nv_bfloat16 g_xhi[Bv * Tv * Hv];      // GEMM A operand, hi part
__device__ __nv_bfloat16 g_xlo[Bv * Tv * Hv];      // GEMM A operand, lo part
__device__ __nv_bfloat16 g_w0hi[FH * Hv];          // W_x0^T [n][k] hi
__device__ __nv_bfloat16 g_w0lo[FH * Hv];
__device__ __nv_bfloat16 g_w1hi[FH * Hv];          // W_x1^T [n][k] hi
__device__ __nv_bfloat16 g_w1lo[FH * Hv];
__device__ float g_hT[2][Hv * Bv];                 // transposed hidden state [k][b]
__device__ ull g_sg[4][4 * 32];                    // [bg][subgroup*32] arrival ctrs
__device__ ull g_rt[4 * 32];                       // [bg] root counters (padded)
__device__ ull g_gen2[4 * 32];                     // [bg] release generations

// ---------------- helpers -----------------------------------------------------
__device__ __forceinline__ uint32_t smem_u32(const void* p) {
    uint32_t a;
    asm("{ .reg .u64 t; cvta.to.shared.u64 t, %1; cvt.u32.u64 %0, t; }" : "=r"(a) : "l"(p));
    return a;
}
__device__ __forceinline__ void cp16(uint32_t dst, const void* src) {
    asm volatile("cp.async.cg.shared.global [%0], [%1], 16;" :: "r"(dst), "l"(src) : "memory");
}
#define CP_COMMIT() asm volatile("cp.async.commit_group;" ::: "memory")
#define CP_WAIT0()  asm volatile("cp.async.wait_group 0;" ::: "memory")
#define CP_WAIT1()  asm volatile("cp.async.wait_group 1;" ::: "memory")

__device__ __forceinline__ void ldsm_x4(uint32_t& r0, uint32_t& r1, uint32_t& r2,
                                        uint32_t& r3, uint32_t addr) {
    asm volatile("ldmatrix.sync.aligned.m8n8.x4.shared.b16 {%0,%1,%2,%3}, [%4];"
                 : "=r"(r0), "=r"(r1), "=r"(r2), "=r"(r3) : "r"(addr));
}
__device__ __forceinline__ void mma16816(float* d, const uint32_t* a, const uint32_t* b) {
    asm volatile(
        "mma.sync.aligned.m16n8k16.row.col.f32.bf16.bf16.f32 "
        "{%0,%1,%2,%3}, {%4,%5,%6,%7}, {%8,%9}, {%0,%1,%2,%3};"
        : "+f"(d[0]), "+f"(d[1]), "+f"(d[2]), "+f"(d[3])
        : "r"(a[0]), "r"(a[1]), "r"(a[2]), "r"(a[3]), "r"(b[0]), "r"(b[1]));
}

// ---------------- packed f32x2 helpers ---------------------------------------
__device__ __forceinline__ ull ffma2(ull a, ull b, ull c) {
    ull d; asm("fma.rn.f32x2 %0, %1, %2, %3;" : "=l"(d) : "l"(a), "l"(b), "l"(c)); return d;
}
__device__ __forceinline__ ull fadd2(ull a, ull b) {
    ull d; asm("add.rn.f32x2 %0, %1, %2;" : "=l"(d) : "l"(a), "l"(b)); return d;
}
__device__ __forceinline__ ull fdup(float x) {
    ull d; asm("mov.b64 %0, {%1, %1};" : "=l"(d) : "f"(x)); return d;
}

// fast gates: MUFU-based, rel err ~1e-6 (NOT tanh.approx: 2^-11 too coarse)
__device__ __forceinline__ float fast_sigmoid(float z) {
    return __fdividef(1.f, 1.f + __expf(-z));
}
__device__ __forceinline__ float fast_tanh(float z) {
    return 1.f - __fdividef(2.f, 1.f + __expf(2.f * z));
}

// ---------------- batch-group-local barrier (32 CTAs: 4 subgroups x 8) -------
__device__ __forceinline__ void bg_barrier(int bg, int sg) {
    __syncthreads();
    if (threadIdx.x == 0) {
        __threadfence();
        ull o = atomicAdd(&g_sg[bg][sg * 32], 1ULL);
        ull gen = o >> 3;                    // 8 CTAs per subgroup
        if ((o & 7ULL) == 7ULL) {
            ull r = atomicAdd(&g_rt[bg * 32], 1ULL);
            if ((r & 3ULL) == 3ULL) {
                __threadfence();
                *(volatile ull*)&g_gen2[bg * 32] = (r >> 2) + 1ULL;
            }
        }
        while (*(volatile ull*)&g_gen2[bg * 32] <= gen) { }
        __threadfence();
    }
    __syncthreads();
}

// ---------------- conversion + pad kernels -----------------------------------
__global__ void ncu_pad_kernel() {}

__global__ void convert_x_kernel(const float* __restrict__ x) {
    const int N2 = Bv * Tv * Hv / 2;
    for (int i = blockIdx.x * blockDim.x + threadIdx.x; i < N2; i += gridDim.x * blockDim.x) {
        float2 v = ((const float2*)x)[i];
        __nv_bfloat16 h0 = __float2bfloat16(v.x);
        __nv_bfloat16 h1 = __float2bfloat16(v.y);
        ((__nv_bfloat162*)g_xhi)[i] = __halves2bfloat162(h0, h1);
        ((__nv_bfloat162*)g_xlo)[i] = __halves2bfloat162(
            __float2bfloat16(v.x - __bfloat162float(h0)),
            __float2bfloat16(v.y - __bfloat162float(h1)));
    }
}

__global__ void convert_w_kernel(const float* __restrict__ W,
                                 __nv_bfloat16* __restrict__ hi,
                                 __nv_bfloat16* __restrict__ lo) {
    for (int i = blockIdx.x * blockDim.x + threadIdx.x; i < Hv * FH; i += gridDim.x * blockDim.x) {
        int k = i >> 11, n = i & (FH - 1);
        float v = W[i];
        __nv_bfloat16 h = __float2bfloat16(v);
        hi[n * Hv + k] = h;
        lo[n * Hv + k] = __float2bfloat16(v - __bfloat162float(h));
    }
}

// ---------------- mma.sync split-bf16 GEMM (3-stage cp.async pipeline) -------
#define AST 72
#define GBUFB (128 * AST * 2)

__global__ __launch_bounds__(256, 2)
void gemm_mma_kernel(const __nv_bfloat16* __restrict__ whi,
                     const __nv_bfloat16* __restrict__ wlo)
{
    extern __shared__ __nv_bfloat16 smb[];
    const int tid = threadIdx.x;
    const int wid = tid >> 5, lane = tid & 31;
    const int bn = blockIdx.x;
    const int bm = blockIdx.y;
    const int wr = wid >> 2;
    const int wc = wid & 3;

    const uint32_t As0 = smem_u32(smb);
    const uint32_t Bs0 = As0 + 3 * GBUFB;

    float acc[4][4][4];
#pragma unroll
    for (int mi = 0; mi < 4; ++mi)
#pragma unroll
        for (int nj = 0; nj < 4; ++nj)
#pragma unroll
            for (int r = 0; r < 4; ++r) acc[mi][nj][r] = 0.f;

    uint32_t a_base[4], b_base[2];
    {
        int arow = (lane & 15);
        int akof = (lane >> 4) * 8;
#pragma unroll
        for (int mi = 0; mi < 4; ++mi)
            a_base[mi] = As0 + ((wr * 64 + mi * 16 + arow) * AST + akof) * 2;
        int brow = (lane & 7) + ((lane >> 4) & 1) * 8;
        int bkof = ((lane >> 3) & 1) * 8;
#pragma unroll
        for (int np = 0; np < 2; ++np)
            b_base[np] = Bs0 + ((wc * 32 + np * 16 + brow) * AST + bkof) * 2;
    }

    const int sr = tid >> 1;
    const int sh = (tid & 1) * 32;

    auto do_stage = [&](int c, int buf) {
        int p = c >> 3, kc = (c & 7) * 64;
        const __nv_bfloat16* Ag = ((p == 2) ? g_xlo : g_xhi) + (size_t)bm * 128 * Hv;
        const __nv_bfloat16* Bg = ((p == 1) ? wlo : whi) + (size_t)bn * 128 * Hv;
#pragma unroll
        for (int u = 0; u < 4; ++u) {
            int co = sh + u * 8;
            cp16(As0 + buf * GBUFB + (sr * AST + co) * 2, Ag + (size_t)sr * Hv + kc + co);
            cp16(Bs0 + buf * GBUFB + (sr * AST + co) * 2, Bg + (size_t)sr * Hv + kc + co);
        }
        CP_COMMIT();
    };

    do_stage(0, 0);
    do_stage(1, 1);
    for (int c = 0; c < 24; ++c) {
        if (c + 1 < 24) CP_WAIT1(); else CP_WAIT0();
        __syncthreads();
        uint32_t bo = (uint32_t)(c % 3) * GBUFB;
#pragma unroll
        for (int ks = 0; ks < 4; ++ks) {
            uint32_t a[4][4], b[2][4];
#pragma unroll
            for (int mi = 0; mi < 4; ++mi)
                ldsm_x4(a[mi][0], a[mi][1], a[mi][2], a[mi][3], a_base[mi] + bo + ks * 32);
#pragma unroll
            for (int np = 0; np < 2; ++np)
                ldsm_x4(b[np][0], b[np][1], b[np][2], b[np][3], b_base[np] + bo + ks * 32);
#pragma unroll
            for (int mi = 0; mi < 4; ++mi) {
#pragma unroll
                for (int nj = 0; nj < 4; ++nj) {
                    uint32_t bf[2] = { b[nj >> 1][(nj & 1) * 2],
                                       b[nj >> 1][(nj & 1) * 2 + 1] };
                    mma16816(acc[mi][nj], a[mi], bf);
                }
            }
        }
        if (c + 2 < 24) do_stage(c + 2, (c + 2) % 3);
    }

    const int erow = lane >> 2;
    const int ecol = (lane & 3) * 2;
#pragma unroll
    for (int mi = 0; mi < 4; ++mi) {
#pragma unroll
        for (int nj = 0; nj < 4; ++nj) {
            int row0 = bm * 128 + wr * 64 + mi * 16 + erow;
            int col  = bn * 128 + wc * 32 + nj * 8 + ecol;
            *(float2*)&g_xproj[(size_t)row0 * FH + col] =
                make_float2(acc[mi][nj][0], acc[mi][nj][1]);
            *(float2*)&g_xproj[(size_t)(row0 + 8) * FH + col] =
                make_float2(acc[mi][nj][2], acc[mi][nj][3]);
        }
    }
}

// ---------------- persistent recurrent LSTM layer ----------------------------
// 128 CTAs = 32 col-groups x 4 batch-groups; barriers are batch-group-local
// (h exchange for a batch slice depends only on CTAs of the same bg).
__global__ __launch_bounds__(NTHR, 1)
void lstm_layer_kernel(const float* __restrict__ Wh,
                       const float* __restrict__ bvec,
                       const float* __restrict__ h_in,
                       const float* __restrict__ c_in,
                       float* __restrict__ seq_out_ext, int seq_to_internal,
                       float* __restrict__ hT_out,
                       float* __restrict__ cT_out)
{
    extern __shared__ float smemf[];
    float* w_s = smemf;                    // [512][68] (64 z-cols used)
    float* h_s = smemf + 512 * 68;         // [512][20] (16 batches used)
    float* z_s = h_s + 512 * 20;           // [64][20]  z[c][b]
    float* c_s = z_s + 64 * 20;            // [256]

    const float* xp = g_xproj;
    const int tid = threadIdx.x;
    const int cg = blockIdx.x & 31;        // col group
    const int bg = blockIdx.x >> 5;        // batch group
    const int sg = cg >> 3;                // barrier subgroup within bg
    const int n0 = cg * 16;                // base hidden column
    const int bb0 = bg * 16;               // base batch
    const uint32_t hs_u32 = smem_u32(h_s);

    for (int idx = tid; idx < 512 * 16; idx += NTHR) {
        int k = idx >> 4, q = idx & 15;
        int gate = q >> 2, j4 = (q & 3) * 4;
        *(float4*)&w_s[k * 68 + gate * 16 + j4] =
            *(const float4*)&Wh[(size_t)k * FH + gate * Hv + n0 + j4];
    }
    if (tid < 256) {
        int b = tid >> 4, j = tid & 15;
        c_s[tid] = c_in[(bb0 + b) * Hv + n0 + j];
        __stcg(&g_hT[0][(n0 + j) * Bv + bb0 + b], h_in[(bb0 + b) * Hv + n0 + j]);
    }
    const float bgi = bvec[0] + bvec[1];
    const float bgf = bvec[2] + bvec[3];
    const float bgg = bvec[4] + bvec[5];
    const float bgo = bvec[6] + bvec[7];

    bg_barrier(bg, sg);

    const int tile = tid >> 5;
    const int ksl  = tid & 31;
    const int c0 = (tile & 7) * 8;
    const int b0 = (tile >> 3) * 8;
    const int eb = tid >> 4, ej = tid & 15;

    for (int t = 0; t < Tv; ++t) {
        const float* hsrc = g_hT[t & 1];
        float* hdst = g_hT[(t & 1) ^ 1];

        // prefetch x-projection first (DRAM latency overlaps staging)
        float x0, x1, x2, x3;
        if (tid < 256) {
            int xbase = ((bb0 + eb) * Tv + t) * FH + n0 + ej;
            x0 = xp[xbase];
            x1 = xp[xbase + Hv];
            x2 = xp[xbase + 2 * Hv];
            x3 = xp[xbase + 3 * Hv];
        }

        // stage h slice [512 k][16 b] (32KB), 2-phase cp.async
#pragma unroll
        for (int u = 0; u < 2; ++u) {
            int f = tid + u * 512;
            cp16(hs_u32 + ((f >> 2) * 20 + (f & 3) * 4) * 4,
                 hsrc + (f >> 2) * Bv + bb0 + (f & 3) * 4);
        }
        CP_COMMIT();
#pragma unroll
        for (int u = 2; u < 4; ++u) {
            int f = tid + u * 512;
            cp16(hs_u32 + ((f >> 2) * 20 + (f & 3) * 4) * 4,
                 hsrc + (f >> 2) * Bv + bb0 + (f & 3) * 4);
        }
        CP_COMMIT();

        ull acc[32];
#pragma unroll
        for (int q = 0; q < 32; ++q) acc[q] = 0ULL;

        CP_WAIT1();
        __syncthreads();
#pragma unroll 4
        for (int i = 0; i < 8; ++i) {
            int k = ksl + (i << 5);
            ulonglong2 h01 = *(const ulonglong2*)&h_s[k * 20 + b0];
            ulonglong2 h23 = *(const ulonglong2*)&h_s[k * 20 + b0 + 4];
            ull hp[4] = { h01.x, h01.y, h23.x, h23.y };
            float wv[8];
            *(float4*)&wv[0] = *(const float4*)&w_s[k * 68 + c0];
            *(float4*)&wv[4] = *(const float4*)&w_s[k * 68 + c0 + 4];
#pragma unroll
            for (int cj = 0; cj < 8; ++cj) {
                ull wd = fdup(wv[cj]);
#pragma unroll
                for (int bp = 0; bp < 4; ++bp)
                    acc[bp * 8 + cj] = ffma2(hp[bp], wd, acc[bp * 8 + cj]);
            }
        }
        CP_WAIT0();
        __syncthreads();
#pragma unroll 4
        for (int i = 8; i < 16; ++i) {
            int k = ksl + (i << 5);
            ulonglong2 h01 = *(const ulonglong2*)&h_s[k * 20 + b0];
            ulonglong2 h23 = *(const ulonglong2*)&h_s[k * 20 + b0 + 4];
            ull hp[4] = { h01.x, h01.y, h23.x, h23.y };
            float wv[8];
            *(float4*)&wv[0] = *(const float4*)&w_s[k * 68 + c0];
            *(float4*)&wv[4] = *(const float4*)&w_s[k * 68 + c0 + 4];
#pragma unroll
            for (int cj = 0; cj < 8; ++cj) {
                ull wd = fdup(wv[cj]);
#pragma unroll
                for (int bp = 0; bp < 4; ++bp)
                    acc[bp * 8 + cj] = ffma2(hp[bp], wd, acc[bp * 8 + cj]);
            }
        }

        // reduce-scatter butterfly: lane ksl ends owning (bp=ksl>>3, cj=ksl&7)
#pragma unroll
        for (int m = 16; m >= 1; m >>= 1) {
            bool hi = (ksl & m) != 0;
#pragma unroll
            for (int j = 0; j < m; ++j) {
                ull keep = hi ? acc[j + m] : acc[j];
                ull send = hi ? acc[j] : acc[j + m];
                ull o = __shfl_xor_sync(0xffffffffu, send, m);
                acc[j] = fadd2(keep, o);
            }
        }
        {
            int bp = ksl >> 3, cj = ksl & 7;
            *(ull*)&z_s[(c0 + cj) * 20 + b0 + 2 * bp] = acc[0];
        }
        __syncthreads();

        // gate epilogue (MUFU-based fast math)
        if (tid < 256) {
            float zi = z_s[(0  + ej) * 20 + eb] + x0 + bgi;
            float zf = z_s[(16 + ej) * 20 + eb] + x1 + bgf;
            float zg = z_s[(32 + ej) * 20 + eb] + x2 + bgg;
            float zo = z_s[(48 + ej) * 20 + eb] + x3 + bgo;
            float ig = fast_sigmoid(zi);
            float fg = fast_sigmoid(zf);
            float gg = fast_tanh(zg);
            float og = fast_sigmoid(zo);
            float cn = fmaf(fg, c_s[tid], ig * gg);
            c_s[tid] = cn;
            float hn = og * fast_tanh(cn);
            __stcg(&hdst[(n0 + ej) * Bv + bb0 + eb], hn);
            size_t o = (size_t)((bb0 + eb) * Tv + t) * Hv + n0 + ej;
            if (seq_to_internal) {
                __nv_bfloat16 hh = __float2bfloat16(hn);
                g_xhi[o] = hh;
                g_xlo[o] = __float2bfloat16(hn - __bfloat162float(hh));
            } else {
                seq_out_ext[o] = hn;
            }
            if (t == Tv - 1) {
                hT_out[(bb0 + eb) * Hv + n0 + ej] = hn;
                cT_out[(bb0 + eb) * Hv + n0 + ej] = cn;
            }
        }
        if (t + 1 < Tv) bg_barrier(bg, sg);
    }
}

// ---------------- launch -----------------------------------------------------
extern "C" void kernel_launch(void* const* d_in, const int* in_sizes, int n_in,
                              void* d_out, int out_size)
{
    const float* x   = (const float*)d_in[0];
    const float* h   = (const float*)d_in[1];
    const float* c   = (const float*)d_in[2];
    const float* Wx0 = (const float*)d_in[3];
    const float* Wh0 = (const float*)d_in[4];
    const float* b0  = (const float*)d_in[5];
    const float* Wx1 = (const float*)d_in[6];
    const float* Wh1 = (const float*)d_in[7];
    const float* b1  = (const float*)d_in[8];
    float* out = (float*)d_out;

    const int LSTM_SMEM = (512 * 68 + 512 * 20 + 64 * 20 + 256) * 4;  // 186368
    cudaFuncSetAttribute(lstm_layer_kernel,
                         cudaFuncAttributeMaxDynamicSharedMemorySize, LSTM_SMEM);
    const int GEMM_SMEM = 6 * GBUFB;   // 110592
    cudaFuncSetAttribute(gemm_mma_kernel,
                         cudaFuncAttributeMaxDynamicSharedMemorySize, GEMM_SMEM);

    float* out1 = out;
    float* newh = out + (size_t)Bv * Tv * Hv;
    float* newc = newh + 2 * Bv * Hv;

    __nv_bfloat16 *w0hi, *w0lo, *w1hi, *w1lo;
    cudaGetSymbolAddress((void**)&w0hi, g_w0hi);
    cudaGetSymbolAddress((void**)&w0lo, g_w0lo);
    cudaGetSymbolAddress((void**)&w1hi, g_w1hi);
    cudaGetSymbolAddress((void**)&w1lo, g_w1lo);

    dim3 gg(FH / 128, (Bv * Tv) / 128);   // (16, 256)

    convert_w_kernel<<<512, 256>>>(Wx0, w0hi, w0lo);
    convert_w_kernel<<<512, 256>>>(Wx1, w1hi, w1lo);
    convert_x_kernel<<<4096, 256>>>(x);
    ncu_pad_kernel<<<1, 32>>>();   // aligns ncu -s 5 onto the lstm kernel

    // Layer 0
    gemm_mma_kernel<<<gg, 256, GEMM_SMEM>>>(w0hi, w0lo);
    lstm_layer_kernel<<<NCTA, NTHR, LSTM_SMEM>>>(
        Wh0, b0, h, c, nullptr, 1, newh, newc);

    // Layer 1
    gemm_mma_kernel<<<gg, 256, GEMM_SMEM>>>(w1hi, w1lo);
    lstm_layer_kernel<<<NCTA, NTHR, LSTM_SMEM>>>(
        Wh1, b1, h + Bv * Hv, c + Bv * Hv, out1, 0,
        newh + Bv * Hv, newc + Bv * Hv);
}

// round 9
// speedup vs baseline: 3.0800x; 1.2888x over previous
#include <cuda_runtime.h>
#include <cuda_bf16.h>
#include <math.h>
#include <cstdint>

#define Bv 64
#define Tv 512
#define Hv 512
#define FH 2048   /* 4*H */

#define NCTA 128
#define NTHR 512

typedef unsigned long long ull;

// ---------------- device scratch ---------------------------------------------
__device__ float g_xproj[Bv * Tv * FH];            // x-projection for current layer
__device__ __nv_bfloat16 g_xhi[Bv * Tv * Hv];      // GEMM A operand, hi part
__device__ __nv_bfloat16 g_xlo[Bv * Tv * Hv];      // GEMM A operand, lo part
__device__ __nv_bfloat16 g_w0hi[FH * Hv];          // W_x0^T [n][k] hi
__device__ __nv_bfloat16 g_w0lo[FH * Hv];
__device__ __nv_bfloat16 g_w1hi[FH * Hv];          // W_x1^T [n][k] hi
__device__ __nv_bfloat16 g_w1lo[FH * Hv];
__device__ __nv_bfloat16 g_wh0hi[FH * Hv];         // W_h0^T [n][k] hi/lo
__device__ __nv_bfloat16 g_wh0lo[FH * Hv];
__device__ __nv_bfloat16 g_wh1hi[FH * Hv];
__device__ __nv_bfloat16 g_wh1lo[FH * Hv];
__device__ __nv_bfloat16 g_hrhi[2][Bv * Hv];       // recurrent h [b][k], hi/lo, dbl-buf
__device__ __nv_bfloat16 g_hrlo[2][Bv * Hv];
__device__ ull g_sg[4][4 * 32];                    // [bg][subgroup*32] arrival ctrs
__device__ ull g_rt[4 * 32];
__device__ ull g_gen2[4 * 32];

// ---------------- helpers -----------------------------------------------------
__device__ __forceinline__ uint32_t smem_u32(const void* p) {
    uint32_t a;
    asm("{ .reg .u64 t; cvta.to.shared.u64 t, %1; cvt.u32.u64 %0, t; }" : "=r"(a) : "l"(p));
    return a;
}
__device__ __forceinline__ void cp16(uint32_t dst, const void* src) {
    asm volatile("cp.async.cg.shared.global [%0], [%1], 16;" :: "r"(dst), "l"(src) : "memory");
}
#define CP_COMMIT() asm volatile("cp.async.commit_group;" ::: "memory")
#define CP_WAIT0()  asm volatile("cp.async.wait_group 0;" ::: "memory")
#define CP_WAIT1()  asm volatile("cp.async.wait_group 1;" ::: "memory")

__device__ __forceinline__ void ldsm_x4(uint32_t& r0, uint32_t& r1, uint32_t& r2,
                                        uint32_t& r3, uint32_t addr) {
    asm volatile("ldmatrix.sync.aligned.m8n8.x4.shared.b16 {%0,%1,%2,%3}, [%4];"
                 : "=r"(r0), "=r"(r1), "=r"(r2), "=r"(r3) : "r"(addr));
}
__device__ __forceinline__ void mma16816(float* d, const uint32_t* a, const uint32_t* b) {
    asm volatile(
        "mma.sync.aligned.m16n8k16.row.col.f32.bf16.bf16.f32 "
        "{%0,%1,%2,%3}, {%4,%5,%6,%7}, {%8,%9}, {%0,%1,%2,%3};"
        : "+f"(d[0]), "+f"(d[1]), "+f"(d[2]), "+f"(d[3])
        : "r"(a[0]), "r"(a[1]), "r"(a[2]), "r"(a[3]), "r"(b[0]), "r"(b[1]));
}

// fast gates: MUFU-based, rel err ~1e-6
__device__ __forceinline__ float fast_sigmoid(float z) {
    return __fdividef(1.f, 1.f + __expf(-z));
}
__device__ __forceinline__ float fast_tanh(float z) {
    return 1.f - __fdividef(2.f, 1.f + __expf(2.f * z));
}

// ---------------- batch-group-local barrier (32 CTAs: 4 subgroups x 8) -------
__device__ __forceinline__ void bg_barrier(int bg, int sg) {
    __syncthreads();
    if (threadIdx.x == 0) {
        __threadfence();
        ull o = atomicAdd(&g_sg[bg][sg * 32], 1ULL);
        ull gen = o >> 3;
        if ((o & 7ULL) == 7ULL) {
            ull r = atomicAdd(&g_rt[bg * 32], 1ULL);
            if ((r & 3ULL) == 3ULL) {
                __threadfence();
                *(volatile ull*)&g_gen2[bg * 32] = (r >> 2) + 1ULL;
            }
        }
        while (*(volatile ull*)&g_gen2[bg * 32] <= gen) { }
        __threadfence();
    }
    __syncthreads();
}

// ---------------- conversion kernels -----------------------------------------
__global__ void convert_x_kernel(const float* __restrict__ x) {
    const int N2 = Bv * Tv * Hv / 2;
    for (int i = blockIdx.x * blockDim.x + threadIdx.x; i < N2; i += gridDim.x * blockDim.x) {
        float2 v = ((const float2*)x)[i];
        __nv_bfloat16 h0 = __float2bfloat16(v.x);
        __nv_bfloat16 h1 = __float2bfloat16(v.y);
        ((__nv_bfloat162*)g_xhi)[i] = __halves2bfloat162(h0, h1);
        ((__nv_bfloat162*)g_xlo)[i] = __halves2bfloat162(
            __float2bfloat16(v.x - __bfloat162float(h0)),
            __float2bfloat16(v.y - __bfloat162float(h1)));
    }
}

__global__ void convert_w_kernel(const float* __restrict__ W,
                                 __nv_bfloat16* __restrict__ hi,
                                 __nv_bfloat16* __restrict__ lo) {
    for (int i = blockIdx.x * blockDim.x + threadIdx.x; i < Hv * FH; i += gridDim.x * blockDim.x) {
        int k = i >> 11, n = i & (FH - 1);
        float v = W[i];
        __nv_bfloat16 h = __float2bfloat16(v);
        hi[n * Hv + k] = h;
        lo[n * Hv + k] = __float2bfloat16(v - __bfloat162float(h));
    }
}

// ---------------- mma.sync split-bf16 GEMM (3-stage cp.async pipeline) -------
#define AST 72
#define GBUFB (128 * AST * 2)

__global__ __launch_bounds__(256, 2)
void gemm_mma_kernel(const __nv_bfloat16* __restrict__ whi,
                     const __nv_bfloat16* __restrict__ wlo)
{
    extern __shared__ __nv_bfloat16 smb[];
    const int tid = threadIdx.x;
    const int wid = tid >> 5, lane = tid & 31;
    const int bn = blockIdx.x;
    const int bm = blockIdx.y;
    const int wr = wid >> 2;
    const int wc = wid & 3;

    const uint32_t As0 = smem_u32(smb);
    const uint32_t Bs0 = As0 + 3 * GBUFB;

    float acc[4][4][4];
#pragma unroll
    for (int mi = 0; mi < 4; ++mi)
#pragma unroll
        for (int nj = 0; nj < 4; ++nj)
#pragma unroll
            for (int r = 0; r < 4; ++r) acc[mi][nj][r] = 0.f;

    uint32_t a_base[4], b_base[2];
    {
        int arow = (lane & 15);
        int akof = (lane >> 4) * 8;
#pragma unroll
        for (int mi = 0; mi < 4; ++mi)
            a_base[mi] = As0 + ((wr * 64 + mi * 16 + arow) * AST + akof) * 2;
        int brow = (lane & 7) + ((lane >> 4) & 1) * 8;
        int bkof = ((lane >> 3) & 1) * 8;
#pragma unroll
        for (int np = 0; np < 2; ++np)
            b_base[np] = Bs0 + ((wc * 32 + np * 16 + brow) * AST + bkof) * 2;
    }

    const int sr = tid >> 1;
    const int sh = (tid & 1) * 32;

    auto do_stage = [&](int c, int buf) {
        int p = c >> 3, kc = (c & 7) * 64;
        const __nv_bfloat16* Ag = ((p == 2) ? g_xlo : g_xhi) + (size_t)bm * 128 * Hv;
        const __nv_bfloat16* Bg = ((p == 1) ? wlo : whi) + (size_t)bn * 128 * Hv;
#pragma unroll
        for (int u = 0; u < 4; ++u) {
            int co = sh + u * 8;
            cp16(As0 + buf * GBUFB + (sr * AST + co) * 2, Ag + (size_t)sr * Hv + kc + co);
            cp16(Bs0 + buf * GBUFB + (sr * AST + co) * 2, Bg + (size_t)sr * Hv + kc + co);
        }
        CP_COMMIT();
    };

    do_stage(0, 0);
    do_stage(1, 1);
    for (int c = 0; c < 24; ++c) {
        if (c + 1 < 24) CP_WAIT1(); else CP_WAIT0();
        __syncthreads();
        uint32_t bo = (uint32_t)(c % 3) * GBUFB;
#pragma unroll
        for (int ks = 0; ks < 4; ++ks) {
            uint32_t a[4][4], b[2][4];
#pragma unroll
            for (int mi = 0; mi < 4; ++mi)
                ldsm_x4(a[mi][0], a[mi][1], a[mi][2], a[mi][3], a_base[mi] + bo + ks * 32);
#pragma unroll
            for (int np = 0; np < 2; ++np)
                ldsm_x4(b[np][0], b[np][1], b[np][2], b[np][3], b_base[np] + bo + ks * 32);
#pragma unroll
            for (int mi = 0; mi < 4; ++mi) {
#pragma unroll
                for (int nj = 0; nj < 4; ++nj) {
                    uint32_t bf[2] = { b[nj >> 1][(nj & 1) * 2],
                                       b[nj >> 1][(nj & 1) * 2 + 1] };
                    mma16816(acc[mi][nj], a[mi], bf);
                }
            }
        }
        if (c + 2 < 24) do_stage(c + 2, (c + 2) % 3);
    }

    const int erow = lane >> 2;
    const int ecol = (lane & 3) * 2;
#pragma unroll
    for (int mi = 0; mi < 4; ++mi) {
#pragma unroll
        for (int nj = 0; nj < 4; ++nj) {
            int row0 = bm * 128 + wr * 64 + mi * 16 + erow;
            int col  = bn * 128 + wc * 32 + nj * 8 + ecol;
            *(float2*)&g_xproj[(size_t)row0 * FH + col] =
                make_float2(acc[mi][nj][0], acc[mi][nj][1]);
            *(float2*)&g_xproj[(size_t)(row0 + 8) * FH + col] =
                make_float2(acc[mi][nj][2], acc[mi][nj][3]);
        }
    }
}

// ---------------- persistent recurrent LSTM layer (tensor-core) --------------
// 128 CTAs = 32 col-groups x 4 batch-groups. Per step per CTA:
// z[64c x 16b] = W^T[64,512] x h[512,16] via mma.m16n8k16, split-bf16 3-pass.
// W slice staged once in smem (bf16 hi/lo, stride 520 -> ldsm conflict-free);
// h kept global as bf16 hi/lo [b][k]; 16 warps = 4 m-tiles x 4 k-quarters.
#define WRS 520                       /* bf16 row stride for W/h in smem */
#define WBUF (64 * WRS * 2)           /* 66560 B per W buffer */
#define HBUF (16 * WRS * 2)           /* 16640 B per h buffer */
#define OFF_H 133120                  /* 2*WBUF */
#define OFF_Z (OFF_H + 2 * HBUF)      /* 166400 */
#define OFF_C (OFF_Z + 4 * 64 * 20 * 4) /* 186880 */
#define LSTM_SMEM (OFF_C + 1024)      /* 187904 */

__global__ __launch_bounds__(NTHR, 1)
void lstm_layer_kernel(const __nv_bfloat16* __restrict__ whT_hi,
                       const __nv_bfloat16* __restrict__ whT_lo,
                       const float* __restrict__ bvec,
                       const float* __restrict__ h_in,
                       const float* __restrict__ c_in,
                       float* __restrict__ seq_out_ext, int seq_to_internal,
                       float* __restrict__ hT_out,
                       float* __restrict__ cT_out)
{
    extern __shared__ float smemf[];
    const uint32_t sb = smem_u32(smemf);
    const uint32_t Wb = sb;                 // W hi at +0, lo at +WBUF
    const uint32_t Hb = sb + OFF_H;         // h hi at +0, lo at +HBUF
    float* z_s = smemf + OFF_Z / 4;         // 4 copies of [64][20]
    float* c_s = smemf + OFF_C / 4;

    const float* xp = g_xproj;
    const int tid = threadIdx.x;
    const int cg = blockIdx.x & 31;
    const int bg = blockIdx.x >> 5;
    const int sg = cg >> 3;
    const int n0 = cg * 16;
    const int bb0 = bg * 16;

    // ---- stage W slice (64 rows x 512 k, hi+lo) via cp.async, once ----
    for (int f = tid; f < 8192; f += NTHR) {
        int buf = f >> 12;                 // 0 hi, 1 lo
        int rem = f & 4095;
        int c = rem >> 6;                  // 0..63
        int off = rem & 63;                // 16B units
        const __nv_bfloat16* src = (buf ? whT_lo : whT_hi)
            + ((size_t)((c >> 4) * Hv + n0 + (c & 15)) << 9) + off * 8;
        cp16(Wb + buf * WBUF + c * (WRS * 2) + off * 16, src);
    }
    CP_COMMIT();

    // ---- c seed + h seed (bf16 hi/lo, [b][k] layout) ----
    if (tid < 256) {
        int b = tid >> 4, j = tid & 15;
        c_s[tid] = c_in[(bb0 + b) * Hv + n0 + j];
        float v = h_in[(bb0 + b) * Hv + n0 + j];
        __nv_bfloat16 hh = __float2bfloat16(v);
        int gi = (bb0 + b) * Hv + n0 + j;
        g_hrhi[0][gi] = hh;
        g_hrlo[0][gi] = __float2bfloat16(v - __bfloat162float(hh));
    }
    const float bgi = bvec[0] + bvec[1];
    const float bgf = bvec[2] + bvec[3];
    const float bgg = bvec[4] + bvec[5];
    const float bgo = bvec[6] + bvec[7];

    CP_WAIT0();
    bg_barrier(bg, sg);

    const int wid = tid >> 5, lane = tid & 31;
    const int mi = wid & 3;                // m-tile (16 z-cols)
    const int kh = wid >> 2;               // k-quarter (128 k)
    const int eb = tid >> 4, ej = tid & 15;

    // ldsm base addresses (copied from gemm_mma_kernel pattern)
    const uint32_t a_rel = (uint32_t)(((mi * 16 + (lane & 15)) * WRS
                                       + kh * 128 + (lane >> 4) * 8) * 2);
    const uint32_t b_rel = (uint32_t)(((((lane & 7) + ((lane >> 4) & 1) * 8)) * WRS
                                       + kh * 128 + ((lane >> 3) & 1) * 8) * 2);

    for (int t = 0; t < Tv; ++t) {
        const __nv_bfloat16* shi = g_hrhi[t & 1];
        const __nv_bfloat16* slo = g_hrlo[t & 1];
        const int dst = (t & 1) ^ 1;

        // prefetch x-projection
        float x0, x1, x2, x3;
        if (tid < 256) {
            int xbase = ((bb0 + eb) * Tv + t) * FH + n0 + ej;
            x0 = xp[xbase];
            x1 = xp[xbase + Hv];
            x2 = xp[xbase + 2 * Hv];
            x3 = xp[xbase + 3 * Hv];
        }

        // stage h slice [16 b][512 k] hi+lo (32KB) via cp.async
#pragma unroll
        for (int u = 0; u < 4; ++u) {
            int f = tid + u * NTHR;        // 0..2047
            int buf = f >> 10;             // 0 hi, 1 lo
            int rem = f & 1023;
            int row = rem >> 6, off = rem & 63;
            const __nv_bfloat16* s = (buf ? slo : shi)
                + ((size_t)(bb0 + row) << 9) + off * 8;
            cp16(Hb + buf * HBUF + row * (WRS * 2) + off * 16, s);
        }
        CP_COMMIT();
        CP_WAIT0();
        __syncthreads();

        // 3-pass split-bf16 mma: Whi*hhi + Wlo*hhi + Whi*hlo
        float acc[2][4];
#pragma unroll
        for (int nj = 0; nj < 2; ++nj)
#pragma unroll
            for (int r = 0; r < 4; ++r) acc[nj][r] = 0.f;

#pragma unroll
        for (int p = 0; p < 3; ++p) {
            uint32_t aa = Wb + a_rel + ((p == 1) ? (uint32_t)WBUF : 0u);
            uint32_t bb = Hb + b_rel + ((p == 2) ? (uint32_t)HBUF : 0u);
#pragma unroll
            for (int ks = 0; ks < 8; ++ks) {
                uint32_t a[4], b[4];
                ldsm_x4(a[0], a[1], a[2], a[3], aa + ks * 32);
                ldsm_x4(b[0], b[1], b[2], b[3], bb + ks * 32);
                mma16816(acc[0], a, b);
                mma16816(acc[1], a, b + 2);
            }
        }

        // write z fragments: copy kh, rows mi*16 + r(+8), batches nj*8 + pair
        {
            int r = lane >> 2, cp2 = (lane & 3) * 2;
            float* zk = z_s + kh * 1280;
#pragma unroll
            for (int nj = 0; nj < 2; ++nj) {
                int b = nj * 8 + cp2;
                *(float2*)&zk[(mi * 16 + r) * 20 + b] =
                    make_float2(acc[nj][0], acc[nj][1]);
                *(float2*)&zk[(mi * 16 + r + 8) * 20 + b] =
                    make_float2(acc[nj][2], acc[nj][3]);
            }
        }
        __syncthreads();

        // gate epilogue: sum 4 k-quarter copies, fast gates
        if (tid < 256) {
            float zi = x0 + bgi, zf = x1 + bgf, zg = x2 + bgg, zo = x3 + bgo;
#pragma unroll
            for (int q = 0; q < 4; ++q) {
                const float* zk = z_s + q * 1280;
                zi += zk[(0  + ej) * 20 + eb];
                zf += zk[(16 + ej) * 20 + eb];
                zg += zk[(32 + ej) * 20 + eb];
                zo += zk[(48 + ej) * 20 + eb];
            }
            float ig = fast_sigmoid(zi);
            float fg = fast_sigmoid(zf);
            float gg = fast_tanh(zg);
            float og = fast_sigmoid(zo);
            float cn = fmaf(fg, c_s[tid], ig * gg);
            c_s[tid] = cn;
            float hn = og * fast_tanh(cn);
            __nv_bfloat16 hh = __float2bfloat16(hn);
            __nv_bfloat16 hl = __float2bfloat16(hn - __bfloat162float(hh));
            int gi = (bb0 + eb) * Hv + n0 + ej;
            g_hrhi[dst][gi] = hh;
            g_hrlo[dst][gi] = hl;
            size_t o = (size_t)((bb0 + eb) * Tv + t) * Hv + n0 + ej;
            if (seq_to_internal) {
                g_xhi[o] = hh;
                g_xlo[o] = hl;
            } else {
                seq_out_ext[o] = hn;
            }
            if (t == Tv - 1) {
                hT_out[(bb0 + eb) * Hv + n0 + ej] = hn;
                cT_out[(bb0 + eb) * Hv + n0 + ej] = cn;
            }
        }
        if (t + 1 < Tv) bg_barrier(bg, sg);
    }
}

// ---------------- launch -----------------------------------------------------
extern "C" void kernel_launch(void* const* d_in, const int* in_sizes, int n_in,
                              void* d_out, int out_size)
{
    const float* x   = (const float*)d_in[0];
    const float* h   = (const float*)d_in[1];
    const float* c   = (const float*)d_in[2];
    const float* Wx0 = (const float*)d_in[3];
    const float* Wh0 = (const float*)d_in[4];
    const float* b0  = (const float*)d_in[5];
    const float* Wx1 = (const float*)d_in[6];
    const float* Wh1 = (const float*)d_in[7];
    const float* b1  = (const float*)d_in[8];
    float* out = (float*)d_out;

    cudaFuncSetAttribute(lstm_layer_kernel,
                         cudaFuncAttributeMaxDynamicSharedMemorySize, LSTM_SMEM);
    const int GEMM_SMEM = 6 * GBUFB;   // 110592
    cudaFuncSetAttribute(gemm_mma_kernel,
                         cudaFuncAttributeMaxDynamicSharedMemorySize, GEMM_SMEM);

    float* out1 = out;
    float* newh = out + (size_t)Bv * Tv * Hv;
    float* newc = newh + 2 * Bv * Hv;

    __nv_bfloat16 *w0hi, *w0lo, *w1hi, *w1lo, *wh0hi, *wh0lo, *wh1hi, *wh1lo;
    cudaGetSymbolAddress((void**)&w0hi, g_w0hi);
    cudaGetSymbolAddress((void**)&w0lo, g_w0lo);
    cudaGetSymbolAddress((void**)&w1hi, g_w1hi);
    cudaGetSymbolAddress((void**)&w1lo, g_w1lo);
    cudaGetSymbolAddress((void**)&wh0hi, g_wh0hi);
    cudaGetSymbolAddress((void**)&wh0lo, g_wh0lo);
    cudaGetSymbolAddress((void**)&wh1hi, g_wh1hi);
    cudaGetSymbolAddress((void**)&wh1lo, g_wh1lo);

    dim3 gg(FH / 128, (Bv * Tv) / 128);   // (16, 256)

    convert_x_kernel<<<4096, 256>>>(x);
    convert_w_kernel<<<512, 256>>>(Wx0, w0hi, w0lo);
    convert_w_kernel<<<512, 256>>>(Wh0, wh0hi, wh0lo);
    convert_w_kernel<<<512, 256>>>(Wx1, w1hi, w1lo);
    convert_w_kernel<<<512, 256>>>(Wh1, wh1hi, wh1lo);

    // Layer 0
    gemm_mma_kernel<<<gg, 256, GEMM_SMEM>>>(w0hi, w0lo);
    lstm_layer_kernel<<<NCTA, NTHR, LSTM_SMEM>>>(
        wh0hi, wh0lo, b0, h, c, nullptr, 1, newh, newc);

    // Layer 1
    gemm_mma_kernel<<<gg, 256, GEMM_SMEM>>>(w1hi, w1lo);
    lstm_layer_kernel<<<NCTA, NTHR, LSTM_SMEM>>>(
        wh1hi, wh1lo, b1, h + Bv * Hv, c + Bv * Hv, out1, 0,
        newh + Bv * Hv, newc + Bv * Hv);
}